// round 8
// baseline (speedup 1.0000x reference)
#include <cuda_runtime.h>
#include <cuda_bf16.h>
#include <cstdint>

#define Bq 2
#define Sq 2048
#define Dq 1024
#define Hq 16
#define HDq 64
#define Mq (Bq*Sq)

// ---------------- global scratch (allocation-free) ----------------
__device__ __align__(16) __nv_bfloat16 gXh[Mq*Dq], gXl[Mq*Dq];
__device__ __align__(16) __nv_bfloat16 gWh[4][Dq*Dq], gWl[4][Dq*Dq];
__device__ __align__(16) __nv_bfloat16 gQh[Mq*Dq], gQl[Mq*Dq];
__device__ __align__(16) __nv_bfloat16 gKh[Mq*Dq], gKl[Mq*Dq];
__device__ __align__(16) __nv_bfloat16 gVh[Mq*Dq], gVl[Mq*Dq];
__device__ __align__(16) __nv_bfloat16 gCh[Mq*Dq], gCl[Mq*Dq];

// ---------------- small helpers ----------------
__device__ __forceinline__ void split2(float x, float y,
                                       uint32_t& hi, uint32_t& lo) {
    __nv_bfloat16 hx = __float2bfloat16_rn(x);
    __nv_bfloat16 hy = __float2bfloat16_rn(y);
    __nv_bfloat162 h2 = __halves2bfloat162(hx, hy);
    __nv_bfloat162 l2 = __halves2bfloat162(
        __float2bfloat16_rn(x - __bfloat162float(hx)),
        __float2bfloat16_rn(y - __bfloat162float(hy)));
    hi = *reinterpret_cast<uint32_t*>(&h2);
    lo = *reinterpret_cast<uint32_t*>(&l2);
}

__device__ __forceinline__ void mma16816(float* c, const uint32_t* a,
                                         uint32_t b0, uint32_t b1) {
    asm volatile("mma.sync.aligned.m16n8k16.row.col.f32.bf16.bf16.f32 "
                 "{%0,%1,%2,%3}, {%4,%5,%6,%7}, {%8,%9}, {%0,%1,%2,%3};"
                 : "+f"(c[0]), "+f"(c[1]), "+f"(c[2]), "+f"(c[3])
                 : "r"(a[0]), "r"(a[1]), "r"(a[2]), "r"(a[3]),
                   "r"(b0), "r"(b1));
}

__device__ __forceinline__ void ldm_x4(uint32_t* r, uint32_t a) {
    asm volatile("ldmatrix.sync.aligned.m8n8.x4.shared.b16 {%0,%1,%2,%3}, [%4];"
                 : "=r"(r[0]), "=r"(r[1]), "=r"(r[2]), "=r"(r[3]) : "r"(a));
}
__device__ __forceinline__ void ldm_x4_t(uint32_t* r, uint32_t a) {
    asm volatile("ldmatrix.sync.aligned.m8n8.x4.trans.shared.b16 {%0,%1,%2,%3}, [%4];"
                 : "=r"(r[0]), "=r"(r[1]), "=r"(r[2]), "=r"(r[3]) : "r"(a));
}

__device__ __forceinline__ uint32_t smem_u32(const void* p) {
    uint32_t a;
    asm("{ .reg .u64 t; cvta.to.shared.u64 t, %1; cvt.u32.u64 %0, t; }"
        : "=r"(a) : "l"(p));
    return a;
}

__device__ __forceinline__ void cp16(uint32_t dst, const void* src) {
    asm volatile("cp.async.cg.shared.global [%0], [%1], 16;" :: "r"(dst), "l"(src));
}
__device__ __forceinline__ void cp_commit() {
    asm volatile("cp.async.commit_group;" ::: "memory");
}

// ---------------------------------------------------------------------------
// split kernels: f32 -> bf16 hi/lo
// ---------------------------------------------------------------------------
__global__ void split_kernel(const float* __restrict__ src,
                             __nv_bfloat16* __restrict__ hi,
                             __nv_bfloat16* __restrict__ lo,
                             int n4, float scale)
{
    int i = blockIdx.x * blockDim.x + threadIdx.x;
    if (i >= n4) return;
    float4 v = ((const float4*)src)[i];
    uint32_t h0, l0, h1, l1;
    split2(v.x * scale, v.y * scale, h0, l0);
    split2(v.z * scale, v.w * scale, h1, l1);
    ((uint2*)hi)[i] = make_uint2(h0, h1);
    ((uint2*)lo)[i] = make_uint2(l0, l1);
}

__global__ void split4_kernel(const float* __restrict__ w0,
                              const float* __restrict__ w1,
                              const float* __restrict__ w2,
                              const float* __restrict__ w3,
                              __nv_bfloat16* __restrict__ hi,
                              __nv_bfloat16* __restrict__ lo, int n4)
{
    int i = blockIdx.x * blockDim.x + threadIdx.x;
    if (i >= n4) return;
    int y = blockIdx.y;
    const float* src = (y == 0) ? w0 : (y == 1) ? w1 : (y == 2) ? w2 : w3;
    float scale = (y == 0) ? 0.125f : 1.0f;
    float4 v = ((const float4*)src)[i];
    uint32_t h0, l0, h1, l1;
    split2(v.x * scale, v.y * scale, h0, l0);
    split2(v.z * scale, v.w * scale, h1, l1);
    size_t o = (size_t)y * (Dq * (size_t)Dq / 4) + i;
    ((uint2*)hi)[o] = make_uint2(h0, h1);
    ((uint2*)lo)[o] = make_uint2(l0, l1);
}

// ---------------------------------------------------------------------------
// bf16x3 GEMM: 128x128 CTA tile, BK=16, 4-stage cp.async pipeline,
// one __syncthreads per iter, prefetch distance 3.
// smem rows: 16 bf16 = 32B data, stride 48B (16B-ALIGNED; conflict-free:
// start banks r*12 mod 32 = {0,12,24,4,16,28,8,20} -> perfect 32-bank cover).
// 2 CTAs/SM (98304*2 = 196608 B < 228 KB).
// ---------------------------------------------------------------------------
#define GST 48
#define ATB (128*GST)          // 6144 bytes per array tile
#define STAGE_B (4*ATB)        // Ah,Al,Bh,Bl = 24576
#define GEMM_SMEM (4*STAGE_B)  // 98304

__global__ void __launch_bounds__(256) gemm_tc(
    const __nv_bfloat16* __restrict__ Ah, const __nv_bfloat16* __restrict__ Al,
    const __nv_bfloat16* __restrict__ Bh, const __nv_bfloat16* __restrict__ Bl,
    const float* __restrict__ bias, float bscale,
    float* __restrict__ outF,
    __nv_bfloat16* __restrict__ outH, __nv_bfloat16* __restrict__ outL,
    int writeF)
{
    extern __shared__ char smem[];
    const uint32_t sb = smem_u32(smem);
    const int tid = threadIdx.x;
    const int wid = tid >> 5, lane = tid & 31;
    const int g = lane >> 2, tig = lane & 3;
    const int q4 = lane >> 3, m8 = lane & 7;
    const int wm = wid & 1, wn = wid >> 1;
    const int m0 = blockIdx.y * 128, n0 = blockIdx.x * 128;

    // loader role: each 64-thread group owns one array; 4 cp16/thread/stage
    const int grp = tid >> 6, tg = tid & 63;
    const __nv_bfloat16* msrc =
        (grp == 0) ? Ah + (size_t)m0 * Dq :
        (grp == 1) ? Al + (size_t)m0 * Dq :
        (grp == 2) ? Bh + (size_t)n0 * Dq : Bl + (size_t)n0 * Dq;
    const uint32_t aoff = grp * ATB;

    // per-lane ldmatrix bases (relative to stage base); all 16B-aligned
    const uint32_t aRel = (uint32_t)((wm*64 + ((q4&1)<<3) + m8) * GST + ((q4>>1)<<4));
    const uint32_t bRel = (uint32_t)(2*ATB + (wn*32 + ((q4>>1)<<3) + m8) * GST + ((q4&1)<<4));

    float acc[4][4][4];
#pragma unroll
    for (int i = 0; i < 4; i++)
#pragma unroll
        for (int j = 0; j < 4; j++)
#pragma unroll
            for (int r = 0; r < 4; r++) acc[i][j][r] = 0.f;

    // prefetch stages 0..2
#pragma unroll
    for (int p = 0; p < 3; p++) {
        const uint32_t stage = sb + p * STAGE_B;
        const int k0 = p * 16;
#pragma unroll
        for (int i = 0; i < 4; i++) {
            int chunk = tg + 64 * i;
            int r = chunk >> 1, c = chunk & 1;
            cp16(stage + aoff + r * GST + c * 16, msrc + (size_t)r * Dq + k0 + c * 8);
        }
        cp_commit();
    }

    for (int it = 0; it < 64; it++) {
        if (it < 62)       asm volatile("cp.async.wait_group 2;" ::: "memory");
        else if (it == 62) asm volatile("cp.async.wait_group 1;" ::: "memory");
        else               asm volatile("cp.async.wait_group 0;" ::: "memory");
        __syncthreads();

        if (it < 61) {
            const uint32_t nstage = sb + ((it + 3) & 3) * STAGE_B;
            const int k0 = (it + 3) * 16;
#pragma unroll
            for (int i = 0; i < 4; i++) {
                int chunk = tg + 64 * i;
                int r = chunk >> 1, c = chunk & 1;
                cp16(nstage + aoff + r * GST + c * 16,
                     msrc + (size_t)r * Dq + k0 + c * 8);
            }
            cp_commit();
        }

        const uint32_t stage = sb + (it & 3) * STAGE_B;
        uint32_t ah[4][4], al[4][4];
#pragma unroll
        for (int i = 0; i < 4; i++) {
            ldm_x4(ah[i], stage + aRel + i * (16*GST));
            ldm_x4(al[i], stage + ATB + aRel + i * (16*GST));
        }
#pragma unroll
        for (int jb = 0; jb < 2; jb++) {
            uint32_t bH[4], bL[4];
            ldm_x4(bH, stage + bRel + jb * (16*GST));
            ldm_x4(bL, stage + ATB + bRel + jb * (16*GST));
#pragma unroll
            for (int i = 0; i < 4; i++) {
                mma16816(acc[i][2*jb],   ah[i], bH[0], bH[1]);
                mma16816(acc[i][2*jb],   ah[i], bL[0], bL[1]);
                mma16816(acc[i][2*jb],   al[i], bH[0], bH[1]);
                mma16816(acc[i][2*jb+1], ah[i], bH[2], bH[3]);
                mma16816(acc[i][2*jb+1], ah[i], bL[2], bL[3]);
                mma16816(acc[i][2*jb+1], al[i], bH[2], bH[3]);
            }
        }
    }

    // epilogue
#pragma unroll
    for (int j = 0; j < 4; j++) {
        int cc = n0 + wn*32 + 8*j + 2*tig;
        float b0 = bias[cc] * bscale, b1 = bias[cc + 1] * bscale;
#pragma unroll
        for (int i = 0; i < 4; i++) {
            int rr = m0 + wm*64 + 16*i + g;
            float v00 = acc[i][j][0] + b0, v01 = acc[i][j][1] + b1;
            float v10 = acc[i][j][2] + b0, v11 = acc[i][j][3] + b1;
            if (writeF) {
                *(float2*)(outF + (size_t)rr * Dq + cc) = make_float2(v00, v01);
                *(float2*)(outF + (size_t)(rr + 8) * Dq + cc) = make_float2(v10, v11);
            } else {
                uint32_t h0, l0, h1, l1;
                split2(v00, v01, h0, l0);
                split2(v10, v11, h1, l1);
                size_t i0 = ((size_t)rr * Dq + cc) >> 1;
                size_t i1 = ((size_t)(rr + 8) * Dq + cc) >> 1;
                ((uint32_t*)outH)[i0] = h0; ((uint32_t*)outL)[i0] = l0;
                ((uint32_t*)outH)[i1] = h1; ((uint32_t*)outL)[i1] = l1;
            }
        }
    }
}

// ---------------------------------------------------------------------------
// Flash attention, bf16x3 mma.sync + ldmatrix, cp.async-pipelined KV.
// No-max softmax: scores bounded (|s| <~ 15 << 88 expf range) -> direct
// exp(s)/sum (shift-invariant, exact). 128 q-rows/CTA, 64-key tiles.
// K double-buffered, V single-buffered. Mask in registers.
// ---------------------------------------------------------------------------
#define ATT_QH 0
#define ATT_QL 18432
#define ATT_K0 36864          // K slot s: hi +s*18432, lo +s*18432+9216
#define ATT_V  73728          // hi +0, lo +9216
#define ATT_SMEM 92160

__global__ void __launch_bounds__(256, 2) attn_kernel(
    const __nv_bfloat16* __restrict__ Qh, const __nv_bfloat16* __restrict__ Ql,
    const __nv_bfloat16* __restrict__ Kh, const __nv_bfloat16* __restrict__ Kl,
    const __nv_bfloat16* __restrict__ Vh, const __nv_bfloat16* __restrict__ Vl,
    const float* __restrict__ mask,
    __nv_bfloat16* __restrict__ Ch, __nv_bfloat16* __restrict__ Cl)
{
    extern __shared__ char smem[];
    const uint32_t sbB = smem_u32(smem);

    const int tid = threadIdx.x;
    const int lane = tid & 31;
    const int wid = tid >> 5;
    const int g = lane >> 2, tig = lane & 3;
    const int bh = blockIdx.y;
    const int b = bh >> 4, h = bh & 15;
    const int q0 = blockIdx.x * 128;

    const size_t baseQ  = ((size_t)(b * Sq + q0)) * Dq + h * HDq;
    const size_t baseKV = ((size_t)(b * Sq)) * Dq + h * HDq;

    const int q4 = lane >> 3, m8 = lane & 7;
    const uint32_t aHb = sbB + ATT_QH + (16*wid + ((q4&1)<<3) + m8)*144 + ((q4>>1)<<4);
    const uint32_t aLb = aHb + (ATT_QL - ATT_QH);
    const uint32_t kRel = (((q4>>1)<<3) + m8)*144 + ((q4&1)<<4);
    const uint32_t vHb = sbB + ATT_V + (((q4&1)<<3) + m8)*144 + ((q4>>1)<<4);
    const uint32_t vLb = vHb + 9216;

    const int hg = tid >> 7, ht = tid & 127;
    const __nv_bfloat16* ksrc = hg ? Kl : Kh;
    const __nv_bfloat16* vsrc = hg ? Vl : Vh;
    const uint32_t hoff = hg * 9216;

    // ---- load Q tile (hi/lo), natural rows ----
    {
        const __nv_bfloat16* src = hg ? Ql : Qh;
        const uint32_t off = hg ? ATT_QL : ATT_QH;
#pragma unroll
        for (int i = 0; i < 8; i++) {
            int chunk = ht + 128 * i;
            int r = chunk >> 3, c = chunk & 7;
            uint4 v = ((const uint4*)(src + baseQ + (size_t)r * Dq))[c];
            *(uint4*)(smem + off + r * 144 + c * 16) = v;
        }
    }

    // preload K tile 0
#pragma unroll
    for (int i = 0; i < 4; i++) {
        int chunk = ht + 128 * i;
        int r = chunk >> 3, c = chunk & 7;
        cp16(sbB + ATT_K0 + hoff + r * 144 + c * 16,
             ksrc + baseKV + (size_t)r * Dq + c * 8);
    }
    cp_commit();

    float l0 = 0.f, l1 = 0.f;
    float o[8][4];
#pragma unroll
    for (int jj = 0; jj < 8; jj++)
#pragma unroll
        for (int r = 0; r < 4; r++) o[jj][r] = 0.f;

    for (int t = 0; t < 32; t++) {
        const int k0 = t * 64;
        asm volatile("cp.async.wait_group 0;" ::: "memory");  // K(t) landed
        __syncthreads();                                      // + PV(t-1) done

        // issue V(t) (completes behind QK+softmax)
#pragma unroll
        for (int i = 0; i < 4; i++) {
            int chunk = ht + 128 * i;
            int r = chunk >> 3, c = chunk & 7;
            cp16(sbB + ATT_V + hoff + r * 144 + c * 16,
                 vsrc + baseKV + (size_t)(k0 + r) * Dq + c * 8);
        }
        cp_commit();

        // mask into registers (hidden behind QK)
        float2 mreg[8];
        {
            const float2* mp = (const float2*)(mask + b * Sq + k0);
#pragma unroll
            for (int j = 0; j < 8; j++) mreg[j] = mp[4*j + tig];
        }

        // ---- S = Q K^T ----
        const uint32_t kHb = sbB + ATT_K0 + (t & 1) * 18432 + kRel;
        const uint32_t kLb = kHb + 9216;
        float s[8][4];
#pragma unroll
        for (int j = 0; j < 8; j++)
#pragma unroll
            for (int r = 0; r < 4; r++) s[j][r] = 0.f;

#pragma unroll
        for (int kb = 0; kb < 4; kb++) {
            uint32_t aH[4], aL[4];
            ldm_x4(aH, aHb + kb * 32);
            ldm_x4(aL, aLb + kb * 32);
#pragma unroll
            for (int jp = 0; jp < 4; jp++) {
                uint32_t bH[4], bL[4];
                ldm_x4(bH, kHb + jp * 2304 + kb * 32);
                ldm_x4(bL, kLb + jp * 2304 + kb * 32);
                mma16816(s[2*jp],   aH, bH[0], bH[1]);
                mma16816(s[2*jp],   aH, bL[0], bL[1]);
                mma16816(s[2*jp],   aL, bH[0], bH[1]);
                mma16816(s[2*jp+1], aH, bH[2], bH[3]);
                mma16816(s[2*jp+1], aH, bL[2], bL[3]);
                mma16816(s[2*jp+1], aL, bH[2], bH[3]);
            }
        }

        // issue K(t+1) (completes behind softmax+PV)
        if (t < 31) {
            const uint32_t kdst = sbB + ATT_K0 + ((t + 1) & 1) * 18432 + hoff;
#pragma unroll
            for (int i = 0; i < 4; i++) {
                int chunk = ht + 128 * i;
                int r = chunk >> 3, c = chunk & 7;
                cp16(kdst + r * 144 + c * 16,
                     ksrc + baseKV + (size_t)(k0 + 64 + r) * Dq + c * 8);
            }
            cp_commit();
        }

        // ---- softmax (no max subtraction; exact for bounded scores) ----
        float sum0 = 0.f, sum1 = 0.f;
#pragma unroll
        for (int j = 0; j < 8; j++) {
            s[j][0] = __expf(s[j][0] + mreg[j].x); sum0 += s[j][0];
            s[j][1] = __expf(s[j][1] + mreg[j].y); sum0 += s[j][1];
            s[j][2] = __expf(s[j][2] + mreg[j].x); sum1 += s[j][2];
            s[j][3] = __expf(s[j][3] + mreg[j].y); sum1 += s[j][3];
        }
        sum0 += __shfl_xor_sync(0xffffffffu, sum0, 1);
        sum0 += __shfl_xor_sync(0xffffffffu, sum0, 2);
        sum1 += __shfl_xor_sync(0xffffffffu, sum1, 1);
        sum1 += __shfl_xor_sync(0xffffffffu, sum1, 2);
        l0 += sum0;
        l1 += sum1;

        // ---- pack P as PV A-fragments (hi/lo) ----
        uint32_t ph[4][4], pl[4][4];
#pragma unroll
        for (int kb = 0; kb < 4; kb++) {
            split2(s[2*kb][0],   s[2*kb][1],   ph[kb][0], pl[kb][0]);
            split2(s[2*kb][2],   s[2*kb][3],   ph[kb][1], pl[kb][1]);
            split2(s[2*kb+1][0], s[2*kb+1][1], ph[kb][2], pl[kb][2]);
            split2(s[2*kb+1][2], s[2*kb+1][3], ph[kb][3], pl[kb][3]);
        }

        // V(t) done (K(t+1) may still be in flight)
        if (t < 31) asm volatile("cp.async.wait_group 1;" ::: "memory");
        else        asm volatile("cp.async.wait_group 0;" ::: "memory");
        __syncthreads();

        // ---- O += P V ----
#pragma unroll
        for (int kb = 0; kb < 4; kb++) {
#pragma unroll
            for (int jp = 0; jp < 4; jp++) {
                uint32_t vH[4], vL[4];
                ldm_x4_t(vH, vHb + kb * 2304 + jp * 32);
                ldm_x4_t(vL, vLb + kb * 2304 + jp * 32);
                mma16816(o[2*jp],   ph[kb], vH[0], vH[1]);
                mma16816(o[2*jp],   ph[kb], vL[0], vL[1]);
                mma16816(o[2*jp],   pl[kb], vH[0], vH[1]);
                mma16816(o[2*jp+1], ph[kb], vH[2], vH[3]);
                mma16816(o[2*jp+1], ph[kb], vL[2], vL[3]);
                mma16816(o[2*jp+1], pl[kb], vH[2], vH[3]);
            }
        }
    }

    // ---- epilogue: ctx as bf16 hi/lo ----
    float inv0 = 1.0f / l0, inv1 = 1.0f / l1;
    size_t row0 = (size_t)(b * Sq + q0 + 16*wid + g);
#pragma unroll
    for (int jj = 0; jj < 8; jj++) {
        int cc = 8*jj + 2*tig;
        uint32_t h0, l0b, h1, l1b;
        split2(o[jj][0] * inv0, o[jj][1] * inv0, h0, l0b);
        split2(o[jj][2] * inv1, o[jj][3] * inv1, h1, l1b);
        size_t i0 = (row0 * Dq + h * HDq + cc) >> 1;
        size_t i1 = ((row0 + 8) * Dq + h * HDq + cc) >> 1;
        ((uint32_t*)Ch)[i0] = h0; ((uint32_t*)Cl)[i0] = l0b;
        ((uint32_t*)Ch)[i1] = h1; ((uint32_t*)Cl)[i1] = l1b;
    }
}

// ---------------------------------------------------------------------------

extern "C" void kernel_launch(void* const* d_in, const int* in_sizes, int n_in,
                              void* d_out, int out_size)
{
    const float* hs   = (const float*)d_in[0];
    const float* mask = (const float*)d_in[1];
    const float* Wq   = (const float*)d_in[2];
    const float* bq   = (const float*)d_in[3];
    const float* Wk   = (const float*)d_in[4];
    const float* bk   = (const float*)d_in[5];
    const float* Wv   = (const float*)d_in[6];
    const float* bv   = (const float*)d_in[7];
    const float* Wo   = (const float*)d_in[8];
    const float* bo   = (const float*)d_in[9];
    float* out = (float*)d_out;

    __nv_bfloat16 *xh, *xl, *wh, *wl, *qh, *ql, *kh, *kl, *vh, *vl, *ch, *cl;
    cudaGetSymbolAddress((void**)&xh, gXh); cudaGetSymbolAddress((void**)&xl, gXl);
    cudaGetSymbolAddress((void**)&wh, gWh); cudaGetSymbolAddress((void**)&wl, gWl);
    cudaGetSymbolAddress((void**)&qh, gQh); cudaGetSymbolAddress((void**)&ql, gQl);
    cudaGetSymbolAddress((void**)&kh, gKh); cudaGetSymbolAddress((void**)&kl, gKl);
    cudaGetSymbolAddress((void**)&vh, gVh); cudaGetSymbolAddress((void**)&vl, gVl);
    cudaGetSymbolAddress((void**)&ch, gCh); cudaGetSymbolAddress((void**)&cl, gCl);

    const int WN = Dq * Dq;

    split_kernel<<<(Mq*Dq/4 + 255)/256, 256>>>(hs, xh, xl, Mq*Dq/4, 1.0f);
    dim3 sgrid((WN/4 + 255)/256, 4);
    split4_kernel<<<sgrid, 256>>>(Wq, Wk, Wv, Wo, wh, wl, WN/4);

    cudaFuncSetAttribute(gemm_tc, cudaFuncAttributeMaxDynamicSharedMemorySize, GEMM_SMEM);
    dim3 ggrid(Dq / 128, Mq / 128);

    gemm_tc<<<ggrid, 256, GEMM_SMEM>>>(xh, xl, wh + 0*WN, wl + 0*WN, bq, 0.125f,
                                       nullptr, qh, ql, 0);
    gemm_tc<<<ggrid, 256, GEMM_SMEM>>>(xh, xl, wh + 1*WN, wl + 1*WN, bk, 1.0f,
                                       nullptr, kh, kl, 0);
    gemm_tc<<<ggrid, 256, GEMM_SMEM>>>(xh, xl, wh + 2*WN, wl + 2*WN, bv, 1.0f,
                                       nullptr, vh, vl, 0);

    cudaFuncSetAttribute(attn_kernel, cudaFuncAttributeMaxDynamicSharedMemorySize, ATT_SMEM);
    dim3 agrid(Sq / 128, Bq * Hq);
    attn_kernel<<<agrid, 256, ATT_SMEM>>>(qh, ql, kh, kl, vh, vl, mask, ch, cl);

    gemm_tc<<<ggrid, 256, GEMM_SMEM>>>(ch, cl, wh + 3*WN, wl + 3*WN, bo, 1.0f,
                                       out, nullptr, nullptr, 1);
}

// round 13
// speedup vs baseline: 1.0669x; 1.0669x over previous
#include <cuda_runtime.h>
#include <cuda_bf16.h>
#include <cstdint>

#define Bq 2
#define Sq 2048
#define Dq 1024
#define Hq 16
#define HDq 64
#define Mq (Bq*Sq)

// ---------------- global scratch (allocation-free) ----------------
__device__ __align__(16) __nv_bfloat16 gXh[Mq*Dq], gXl[Mq*Dq];
__device__ __align__(16) __nv_bfloat16 gWh[4][Dq*Dq], gWl[4][Dq*Dq];
__device__ __align__(16) __nv_bfloat16 gQh[Mq*Dq], gQl[Mq*Dq];
__device__ __align__(16) __nv_bfloat16 gKh[Mq*Dq], gKl[Mq*Dq];
__device__ __align__(16) __nv_bfloat16 gVh[Mq*Dq], gVl[Mq*Dq];
__device__ __align__(16) __nv_bfloat16 gCh[Mq*Dq], gCl[Mq*Dq];

// ---------------- small helpers ----------------
__device__ __forceinline__ void split2(float x, float y,
                                       uint32_t& hi, uint32_t& lo) {
    __nv_bfloat16 hx = __float2bfloat16_rn(x);
    __nv_bfloat16 hy = __float2bfloat16_rn(y);
    __nv_bfloat162 h2 = __halves2bfloat162(hx, hy);
    __nv_bfloat162 l2 = __halves2bfloat162(
        __float2bfloat16_rn(x - __bfloat162float(hx)),
        __float2bfloat16_rn(y - __bfloat162float(hy)));
    hi = *reinterpret_cast<uint32_t*>(&h2);
    lo = *reinterpret_cast<uint32_t*>(&l2);
}

__device__ __forceinline__ void mma16816(float* c, const uint32_t* a,
                                         uint32_t b0, uint32_t b1) {
    asm volatile("mma.sync.aligned.m16n8k16.row.col.f32.bf16.bf16.f32 "
                 "{%0,%1,%2,%3}, {%4,%5,%6,%7}, {%8,%9}, {%0,%1,%2,%3};"
                 : "+f"(c[0]), "+f"(c[1]), "+f"(c[2]), "+f"(c[3])
                 : "r"(a[0]), "r"(a[1]), "r"(a[2]), "r"(a[3]),
                   "r"(b0), "r"(b1));
}

__device__ __forceinline__ void ldm_x4(uint32_t* r, uint32_t a) {
    asm volatile("ldmatrix.sync.aligned.m8n8.x4.shared.b16 {%0,%1,%2,%3}, [%4];"
                 : "=r"(r[0]), "=r"(r[1]), "=r"(r[2]), "=r"(r[3]) : "r"(a));
}
__device__ __forceinline__ void ldm_x4_t(uint32_t* r, uint32_t a) {
    asm volatile("ldmatrix.sync.aligned.m8n8.x4.trans.shared.b16 {%0,%1,%2,%3}, [%4];"
                 : "=r"(r[0]), "=r"(r[1]), "=r"(r[2]), "=r"(r[3]) : "r"(a));
}

__device__ __forceinline__ uint32_t smem_u32(const void* p) {
    uint32_t a;
    asm("{ .reg .u64 t; cvta.to.shared.u64 t, %1; cvt.u32.u64 %0, t; }"
        : "=r"(a) : "l"(p));
    return a;
}

__device__ __forceinline__ void cp16(uint32_t dst, const void* src) {
    asm volatile("cp.async.cg.shared.global [%0], [%1], 16;" :: "r"(dst), "l"(src));
}
__device__ __forceinline__ void cp_commit() {
    asm volatile("cp.async.commit_group;" ::: "memory");
}

// ---------------------------------------------------------------------------
// split kernels: f32 -> bf16 hi/lo
// ---------------------------------------------------------------------------
__global__ void split_kernel(const float* __restrict__ src,
                             __nv_bfloat16* __restrict__ hi,
                             __nv_bfloat16* __restrict__ lo,
                             int n4, float scale)
{
    int i = blockIdx.x * blockDim.x + threadIdx.x;
    if (i >= n4) return;
    float4 v = ((const float4*)src)[i];
    uint32_t h0, l0, h1, l1;
    split2(v.x * scale, v.y * scale, h0, l0);
    split2(v.z * scale, v.w * scale, h1, l1);
    ((uint2*)hi)[i] = make_uint2(h0, h1);
    ((uint2*)lo)[i] = make_uint2(l0, l1);
}

__global__ void split4_kernel(const float* __restrict__ w0,
                              const float* __restrict__ w1,
                              const float* __restrict__ w2,
                              const float* __restrict__ w3,
                              __nv_bfloat16* __restrict__ hi,
                              __nv_bfloat16* __restrict__ lo, int n4)
{
    int i = blockIdx.x * blockDim.x + threadIdx.x;
    if (i >= n4) return;
    int y = blockIdx.y;
    const float* src = (y == 0) ? w0 : (y == 1) ? w1 : (y == 2) ? w2 : w3;
    float scale = (y == 0) ? 0.125f : 1.0f;
    float4 v = ((const float4*)src)[i];
    uint32_t h0, l0, h1, l1;
    split2(v.x * scale, v.y * scale, h0, l0);
    split2(v.z * scale, v.w * scale, h1, l1);
    size_t o = (size_t)y * (Dq * (size_t)Dq / 4) + i;
    ((uint2*)hi)[o] = make_uint2(h0, h1);
    ((uint2*)lo)[o] = make_uint2(l0, l1);
}

// ---------------------------------------------------------------------------
// bf16x3 GEMM: 128x128 CTA tile, BK=16, 4-stage cp.async pipeline,
// one __syncthreads per iter, prefetch distance 3.
// __launch_bounds__(256, 2): force <=128 regs so 2 CTAs/SM fit the 64K
// register file (R8 regression: 134 regs -> 1 CTA/SM -> tensor 37%).
// smem rows: 16 bf16 = 32B data, stride 48B (16B-aligned, conflict-free).
// 2 CTAs/SM: 98304*2 = 196608 B < 227 KB.
// ---------------------------------------------------------------------------
#define GST 48
#define ATB (128*GST)          // 6144 bytes per array tile
#define STAGE_B (4*ATB)        // Ah,Al,Bh,Bl = 24576
#define GEMM_SMEM (4*STAGE_B)  // 98304

__global__ void __launch_bounds__(256, 2) gemm_tc(
    const __nv_bfloat16* __restrict__ Ah, const __nv_bfloat16* __restrict__ Al,
    const __nv_bfloat16* __restrict__ Bh, const __nv_bfloat16* __restrict__ Bl,
    const float* __restrict__ bias, float bscale,
    float* __restrict__ outF,
    __nv_bfloat16* __restrict__ outH, __nv_bfloat16* __restrict__ outL,
    int writeF)
{
    extern __shared__ char smem[];
    const uint32_t sb = smem_u32(smem);
    const int tid = threadIdx.x;
    const int wid = tid >> 5, lane = tid & 31;
    const int g = lane >> 2, tig = lane & 3;
    const int q4 = lane >> 3, m8 = lane & 7;
    const int wm = wid & 1, wn = wid >> 1;
    const int m0 = blockIdx.y * 128, n0 = blockIdx.x * 128;

    // loader role: each 64-thread group owns one array; 4 cp16/thread/stage
    const int grp = tid >> 6, tg = tid & 63;
    const __nv_bfloat16* msrc =
        (grp == 0) ? Ah + (size_t)m0 * Dq :
        (grp == 1) ? Al + (size_t)m0 * Dq :
        (grp == 2) ? Bh + (size_t)n0 * Dq : Bl + (size_t)n0 * Dq;
    const uint32_t aoff = grp * ATB;

    // per-lane ldmatrix bases (relative to stage base); all 16B-aligned
    const uint32_t aRel = (uint32_t)((wm*64 + ((q4&1)<<3) + m8) * GST + ((q4>>1)<<4));
    const uint32_t bRel = (uint32_t)(2*ATB + (wn*32 + ((q4>>1)<<3) + m8) * GST + ((q4&1)<<4));

    float acc[4][4][4];
#pragma unroll
    for (int i = 0; i < 4; i++)
#pragma unroll
        for (int j = 0; j < 4; j++)
#pragma unroll
            for (int r = 0; r < 4; r++) acc[i][j][r] = 0.f;

    // prefetch stages 0..2
#pragma unroll
    for (int p = 0; p < 3; p++) {
        const uint32_t stage = sb + p * STAGE_B;
        const int k0 = p * 16;
#pragma unroll
        for (int i = 0; i < 4; i++) {
            int chunk = tg + 64 * i;
            int r = chunk >> 1, c = chunk & 1;
            cp16(stage + aoff + r * GST + c * 16, msrc + (size_t)r * Dq + k0 + c * 8);
        }
        cp_commit();
    }

    for (int it = 0; it < 64; it++) {
        if (it < 62)       asm volatile("cp.async.wait_group 2;" ::: "memory");
        else if (it == 62) asm volatile("cp.async.wait_group 1;" ::: "memory");
        else               asm volatile("cp.async.wait_group 0;" ::: "memory");
        __syncthreads();

        if (it < 61) {
            const uint32_t nstage = sb + ((it + 3) & 3) * STAGE_B;
            const int k0 = (it + 3) * 16;
#pragma unroll
            for (int i = 0; i < 4; i++) {
                int chunk = tg + 64 * i;
                int r = chunk >> 1, c = chunk & 1;
                cp16(nstage + aoff + r * GST + c * 16,
                     msrc + (size_t)r * Dq + k0 + c * 8);
            }
            cp_commit();
        }

        const uint32_t stage = sb + (it & 3) * STAGE_B;
        uint32_t ah[4][4], al[4][4];
#pragma unroll
        for (int i = 0; i < 4; i++) {
            ldm_x4(ah[i], stage + aRel + i * (16*GST));
            ldm_x4(al[i], stage + ATB + aRel + i * (16*GST));
        }
#pragma unroll
        for (int jb = 0; jb < 2; jb++) {
            uint32_t bH[4], bL[4];
            ldm_x4(bH, stage + bRel + jb * (16*GST));
            ldm_x4(bL, stage + ATB + bRel + jb * (16*GST));
#pragma unroll
            for (int i = 0; i < 4; i++) {
                mma16816(acc[i][2*jb],   ah[i], bH[0], bH[1]);
                mma16816(acc[i][2*jb],   ah[i], bL[0], bL[1]);
                mma16816(acc[i][2*jb],   al[i], bH[0], bH[1]);
                mma16816(acc[i][2*jb+1], ah[i], bH[2], bH[3]);
                mma16816(acc[i][2*jb+1], ah[i], bL[2], bL[3]);
                mma16816(acc[i][2*jb+1], al[i], bH[2], bH[3]);
            }
        }
    }

    // epilogue
#pragma unroll
    for (int j = 0; j < 4; j++) {
        int cc = n0 + wn*32 + 8*j + 2*tig;
        float b0 = bias[cc] * bscale, b1 = bias[cc + 1] * bscale;
#pragma unroll
        for (int i = 0; i < 4; i++) {
            int rr = m0 + wm*64 + 16*i + g;
            float v00 = acc[i][j][0] + b0, v01 = acc[i][j][1] + b1;
            float v10 = acc[i][j][2] + b0, v11 = acc[i][j][3] + b1;
            if (writeF) {
                *(float2*)(outF + (size_t)rr * Dq + cc) = make_float2(v00, v01);
                *(float2*)(outF + (size_t)(rr + 8) * Dq + cc) = make_float2(v10, v11);
            } else {
                uint32_t h0, l0, h1, l1;
                split2(v00, v01, h0, l0);
                split2(v10, v11, h1, l1);
                size_t i0 = ((size_t)rr * Dq + cc) >> 1;
                size_t i1 = ((size_t)(rr + 8) * Dq + cc) >> 1;
                ((uint32_t*)outH)[i0] = h0; ((uint32_t*)outL)[i0] = l0;
                ((uint32_t*)outH)[i1] = h1; ((uint32_t*)outL)[i1] = l1;
            }
        }
    }
}

// ---------------------------------------------------------------------------
// Flash attention, bf16x3 mma.sync + ldmatrix, cp.async-pipelined KV.
// No-max softmax: scores bounded (|s| <~ 15 << 88 expf range) -> direct
// exp(s)/sum (shift-invariant, exact). 128 q-rows/CTA, 64-key tiles.
// K double-buffered, V single-buffered. Mask in registers.
// ---------------------------------------------------------------------------
#define ATT_QH 0
#define ATT_QL 18432
#define ATT_K0 36864          // K slot s: hi +s*18432, lo +s*18432+9216
#define ATT_V  73728          // hi +0, lo +9216
#define ATT_SMEM 92160

__global__ void __launch_bounds__(256, 2) attn_kernel(
    const __nv_bfloat16* __restrict__ Qh, const __nv_bfloat16* __restrict__ Ql,
    const __nv_bfloat16* __restrict__ Kh, const __nv_bfloat16* __restrict__ Kl,
    const __nv_bfloat16* __restrict__ Vh, const __nv_bfloat16* __restrict__ Vl,
    const float* __restrict__ mask,
    __nv_bfloat16* __restrict__ Ch, __nv_bfloat16* __restrict__ Cl)
{
    extern __shared__ char smem[];
    const uint32_t sbB = smem_u32(smem);

    const int tid = threadIdx.x;
    const int lane = tid & 31;
    const int wid = tid >> 5;
    const int g = lane >> 2, tig = lane & 3;
    const int bh = blockIdx.y;
    const int b = bh >> 4, h = bh & 15;
    const int q0 = blockIdx.x * 128;

    const size_t baseQ  = ((size_t)(b * Sq + q0)) * Dq + h * HDq;
    const size_t baseKV = ((size_t)(b * Sq)) * Dq + h * HDq;

    const int q4 = lane >> 3, m8 = lane & 7;
    const uint32_t aHb = sbB + ATT_QH + (16*wid + ((q4&1)<<3) + m8)*144 + ((q4>>1)<<4);
    const uint32_t aLb = aHb + (ATT_QL - ATT_QH);
    const uint32_t kRel = (((q4>>1)<<3) + m8)*144 + ((q4&1)<<4);
    const uint32_t vHb = sbB + ATT_V + (((q4&1)<<3) + m8)*144 + ((q4>>1)<<4);
    const uint32_t vLb = vHb + 9216;

    const int hg = tid >> 7, ht = tid & 127;
    const __nv_bfloat16* ksrc = hg ? Kl : Kh;
    const __nv_bfloat16* vsrc = hg ? Vl : Vh;
    const uint32_t hoff = hg * 9216;

    // ---- load Q tile (hi/lo), natural rows ----
    {
        const __nv_bfloat16* src = hg ? Ql : Qh;
        const uint32_t off = hg ? ATT_QL : ATT_QH;
#pragma unroll
        for (int i = 0; i < 8; i++) {
            int chunk = ht + 128 * i;
            int r = chunk >> 3, c = chunk & 7;
            uint4 v = ((const uint4*)(src + baseQ + (size_t)r * Dq))[c];
            *(uint4*)(smem + off + r * 144 + c * 16) = v;
        }
    }

    // preload K tile 0
#pragma unroll
    for (int i = 0; i < 4; i++) {
        int chunk = ht + 128 * i;
        int r = chunk >> 3, c = chunk & 7;
        cp16(sbB + ATT_K0 + hoff + r * 144 + c * 16,
             ksrc + baseKV + (size_t)r * Dq + c * 8);
    }
    cp_commit();

    float l0 = 0.f, l1 = 0.f;
    float o[8][4];
#pragma unroll
    for (int jj = 0; jj < 8; jj++)
#pragma unroll
        for (int r = 0; r < 4; r++) o[jj][r] = 0.f;

    for (int t = 0; t < 32; t++) {
        const int k0 = t * 64;
        asm volatile("cp.async.wait_group 0;" ::: "memory");  // K(t) landed
        __syncthreads();                                      // + PV(t-1) done

        // issue V(t) (completes behind QK+softmax)
#pragma unroll
        for (int i = 0; i < 4; i++) {
            int chunk = ht + 128 * i;
            int r = chunk >> 3, c = chunk & 7;
            cp16(sbB + ATT_V + hoff + r * 144 + c * 16,
                 vsrc + baseKV + (size_t)(k0 + r) * Dq + c * 8);
        }
        cp_commit();

        // mask into registers (hidden behind QK)
        float2 mreg[8];
        {
            const float2* mp = (const float2*)(mask + b * Sq + k0);
#pragma unroll
            for (int j = 0; j < 8; j++) mreg[j] = mp[4*j + tig];
        }

        // ---- S = Q K^T ----
        const uint32_t kHb = sbB + ATT_K0 + (t & 1) * 18432 + kRel;
        const uint32_t kLb = kHb + 9216;
        float s[8][4];
#pragma unroll
        for (int j = 0; j < 8; j++)
#pragma unroll
            for (int r = 0; r < 4; r++) s[j][r] = 0.f;

#pragma unroll
        for (int kb = 0; kb < 4; kb++) {
            uint32_t aH[4], aL[4];
            ldm_x4(aH, aHb + kb * 32);
            ldm_x4(aL, aLb + kb * 32);
#pragma unroll
            for (int jp = 0; jp < 4; jp++) {
                uint32_t bH[4], bL[4];
                ldm_x4(bH, kHb + jp * 2304 + kb * 32);
                ldm_x4(bL, kLb + jp * 2304 + kb * 32);
                mma16816(s[2*jp],   aH, bH[0], bH[1]);
                mma16816(s[2*jp],   aH, bL[0], bL[1]);
                mma16816(s[2*jp],   aL, bH[0], bH[1]);
                mma16816(s[2*jp+1], aH, bH[2], bH[3]);
                mma16816(s[2*jp+1], aH, bL[2], bL[3]);
                mma16816(s[2*jp+1], aL, bH[2], bH[3]);
            }
        }

        // issue K(t+1) (completes behind softmax+PV)
        if (t < 31) {
            const uint32_t kdst = sbB + ATT_K0 + ((t + 1) & 1) * 18432 + hoff;
#pragma unroll
            for (int i = 0; i < 4; i++) {
                int chunk = ht + 128 * i;
                int r = chunk >> 3, c = chunk & 7;
                cp16(kdst + r * 144 + c * 16,
                     ksrc + baseKV + (size_t)(k0 + 64 + r) * Dq + c * 8);
            }
            cp_commit();
        }

        // ---- softmax (no max subtraction; exact for bounded scores) ----
        float sum0 = 0.f, sum1 = 0.f;
#pragma unroll
        for (int j = 0; j < 8; j++) {
            s[j][0] = __expf(s[j][0] + mreg[j].x); sum0 += s[j][0];
            s[j][1] = __expf(s[j][1] + mreg[j].y); sum0 += s[j][1];
            s[j][2] = __expf(s[j][2] + mreg[j].x); sum1 += s[j][2];
            s[j][3] = __expf(s[j][3] + mreg[j].y); sum1 += s[j][3];
        }
        sum0 += __shfl_xor_sync(0xffffffffu, sum0, 1);
        sum0 += __shfl_xor_sync(0xffffffffu, sum0, 2);
        sum1 += __shfl_xor_sync(0xffffffffu, sum1, 1);
        sum1 += __shfl_xor_sync(0xffffffffu, sum1, 2);
        l0 += sum0;
        l1 += sum1;

        // ---- pack P as PV A-fragments (hi/lo) ----
        uint32_t ph[4][4], pl[4][4];
#pragma unroll
        for (int kb = 0; kb < 4; kb++) {
            split2(s[2*kb][0],   s[2*kb][1],   ph[kb][0], pl[kb][0]);
            split2(s[2*kb][2],   s[2*kb][3],   ph[kb][1], pl[kb][1]);
            split2(s[2*kb+1][0], s[2*kb+1][1], ph[kb][2], pl[kb][2]);
            split2(s[2*kb+1][2], s[2*kb+1][3], ph[kb][3], pl[kb][3]);
        }

        // V(t) done (K(t+1) may still be in flight)
        if (t < 31) asm volatile("cp.async.wait_group 1;" ::: "memory");
        else        asm volatile("cp.async.wait_group 0;" ::: "memory");
        __syncthreads();

        // ---- O += P V ----
#pragma unroll
        for (int kb = 0; kb < 4; kb++) {
#pragma unroll
            for (int jp = 0; jp < 4; jp++) {
                uint32_t vH[4], vL[4];
                ldm_x4_t(vH, vHb + kb * 2304 + jp * 32);
                ldm_x4_t(vL, vLb + kb * 2304 + jp * 32);
                mma16816(o[2*jp],   ph[kb], vH[0], vH[1]);
                mma16816(o[2*jp],   ph[kb], vL[0], vL[1]);
                mma16816(o[2*jp],   pl[kb], vH[0], vH[1]);
                mma16816(o[2*jp+1], ph[kb], vH[2], vH[3]);
                mma16816(o[2*jp+1], ph[kb], vL[2], vL[3]);
                mma16816(o[2*jp+1], pl[kb], vH[2], vH[3]);
            }
        }
    }

    // ---- epilogue: ctx as bf16 hi/lo ----
    float inv0 = 1.0f / l0, inv1 = 1.0f / l1;
    size_t row0 = (size_t)(b * Sq + q0 + 16*wid + g);
#pragma unroll
    for (int jj = 0; jj < 8; jj++) {
        int cc = 8*jj + 2*tig;
        uint32_t h0, l0b, h1, l1b;
        split2(o[jj][0] * inv0, o[jj][1] * inv0, h0, l0b);
        split2(o[jj][2] * inv1, o[jj][3] * inv1, h1, l1b);
        size_t i0 = (row0 * Dq + h * HDq + cc) >> 1;
        size_t i1 = ((row0 + 8) * Dq + h * HDq + cc) >> 1;
        ((uint32_t*)Ch)[i0] = h0; ((uint32_t*)Cl)[i0] = l0b;
        ((uint32_t*)Ch)[i1] = h1; ((uint32_t*)Cl)[i1] = l1b;
    }
}

// ---------------------------------------------------------------------------

extern "C" void kernel_launch(void* const* d_in, const int* in_sizes, int n_in,
                              void* d_out, int out_size)
{
    const float* hs   = (const float*)d_in[0];
    const float* mask = (const float*)d_in[1];
    const float* Wq   = (const float*)d_in[2];
    const float* bq   = (const float*)d_in[3];
    const float* Wk   = (const float*)d_in[4];
    const float* bk   = (const float*)d_in[5];
    const float* Wv   = (const float*)d_in[6];
    const float* bv   = (const float*)d_in[7];
    const float* Wo   = (const float*)d_in[8];
    const float* bo   = (const float*)d_in[9];
    float* out = (float*)d_out;

    __nv_bfloat16 *xh, *xl, *wh, *wl, *qh, *ql, *kh, *kl, *vh, *vl, *ch, *cl;
    cudaGetSymbolAddress((void**)&xh, gXh); cudaGetSymbolAddress((void**)&xl, gXl);
    cudaGetSymbolAddress((void**)&wh, gWh); cudaGetSymbolAddress((void**)&wl, gWl);
    cudaGetSymbolAddress((void**)&qh, gQh); cudaGetSymbolAddress((void**)&ql, gQl);
    cudaGetSymbolAddress((void**)&kh, gKh); cudaGetSymbolAddress((void**)&kl, gKl);
    cudaGetSymbolAddress((void**)&vh, gVh); cudaGetSymbolAddress((void**)&vl, gVl);
    cudaGetSymbolAddress((void**)&ch, gCh); cudaGetSymbolAddress((void**)&cl, gCl);

    const int WN = Dq * Dq;

    split_kernel<<<(Mq*Dq/4 + 255)/256, 256>>>(hs, xh, xl, Mq*Dq/4, 1.0f);
    dim3 sgrid((WN/4 + 255)/256, 4);
    split4_kernel<<<sgrid, 256>>>(Wq, Wk, Wv, Wo, wh, wl, WN/4);

    cudaFuncSetAttribute(gemm_tc, cudaFuncAttributeMaxDynamicSharedMemorySize, GEMM_SMEM);
    dim3 ggrid(Dq / 128, Mq / 128);

    gemm_tc<<<ggrid, 256, GEMM_SMEM>>>(xh, xl, wh + 0*WN, wl + 0*WN, bq, 0.125f,
                                       nullptr, qh, ql, 0);
    gemm_tc<<<ggrid, 256, GEMM_SMEM>>>(xh, xl, wh + 1*WN, wl + 1*WN, bk, 1.0f,
                                       nullptr, kh, kl, 0);
    gemm_tc<<<ggrid, 256, GEMM_SMEM>>>(xh, xl, wh + 2*WN, wl + 2*WN, bv, 1.0f,
                                       nullptr, vh, vl, 0);

    cudaFuncSetAttribute(attn_kernel, cudaFuncAttributeMaxDynamicSharedMemorySize, ATT_SMEM);
    dim3 agrid(Sq / 128, Bq * Hq);
    attn_kernel<<<agrid, 256, ATT_SMEM>>>(qh, ql, kh, kl, vh, vl, mask, ch, cl);

    gemm_tc<<<ggrid, 256, GEMM_SMEM>>>(ch, cl, wh + 3*WN, wl + 3*WN, bo, 1.0f,
                                       out, nullptr, nullptr, 1);
}

// round 14
// speedup vs baseline: 1.1835x; 1.1092x over previous
#include <cuda_runtime.h>
#include <cuda_bf16.h>
#include <cstdint>

#define Bq 2
#define Sq 2048
#define Dq 1024
#define Hq 16
#define HDq 64
#define Mq (Bq*Sq)

// ---------------- global scratch (allocation-free) ----------------
__device__ __align__(16) __nv_bfloat16 gXh[Mq*Dq], gXl[Mq*Dq];
__device__ __align__(16) __nv_bfloat16 gWh[4][Dq*Dq], gWl[4][Dq*Dq];
__device__ __align__(16) __nv_bfloat16 gQh[Mq*Dq], gQl[Mq*Dq];
__device__ __align__(16) __nv_bfloat16 gKh[Mq*Dq], gKl[Mq*Dq];
__device__ __align__(16) __nv_bfloat16 gVh[Mq*Dq], gVl[Mq*Dq];
__device__ __align__(16) __nv_bfloat16 gCh[Mq*Dq], gCl[Mq*Dq];

// ---------------- small helpers ----------------
__device__ __forceinline__ void split2(float x, float y,
                                       uint32_t& hi, uint32_t& lo) {
    __nv_bfloat16 hx = __float2bfloat16_rn(x);
    __nv_bfloat16 hy = __float2bfloat16_rn(y);
    __nv_bfloat162 h2 = __halves2bfloat162(hx, hy);
    __nv_bfloat162 l2 = __halves2bfloat162(
        __float2bfloat16_rn(x - __bfloat162float(hx)),
        __float2bfloat16_rn(y - __bfloat162float(hy)));
    hi = *reinterpret_cast<uint32_t*>(&h2);
    lo = *reinterpret_cast<uint32_t*>(&l2);
}

__device__ __forceinline__ void mma16816(float* c, const uint32_t* a,
                                         uint32_t b0, uint32_t b1) {
    asm volatile("mma.sync.aligned.m16n8k16.row.col.f32.bf16.bf16.f32 "
                 "{%0,%1,%2,%3}, {%4,%5,%6,%7}, {%8,%9}, {%0,%1,%2,%3};"
                 : "+f"(c[0]), "+f"(c[1]), "+f"(c[2]), "+f"(c[3])
                 : "r"(a[0]), "r"(a[1]), "r"(a[2]), "r"(a[3]),
                   "r"(b0), "r"(b1));
}

__device__ __forceinline__ void ldm_x4(uint32_t* r, uint32_t a) {
    asm volatile("ldmatrix.sync.aligned.m8n8.x4.shared.b16 {%0,%1,%2,%3}, [%4];"
                 : "=r"(r[0]), "=r"(r[1]), "=r"(r[2]), "=r"(r[3]) : "r"(a));
}
__device__ __forceinline__ void ldm_x4_t(uint32_t* r, uint32_t a) {
    asm volatile("ldmatrix.sync.aligned.m8n8.x4.trans.shared.b16 {%0,%1,%2,%3}, [%4];"
                 : "=r"(r[0]), "=r"(r[1]), "=r"(r[2]), "=r"(r[3]) : "r"(a));
}

__device__ __forceinline__ uint32_t smem_u32(const void* p) {
    uint32_t a;
    asm("{ .reg .u64 t; cvta.to.shared.u64 t, %1; cvt.u32.u64 %0, t; }"
        : "=r"(a) : "l"(p));
    return a;
}

__device__ __forceinline__ void cp16(uint32_t dst, const void* src) {
    asm volatile("cp.async.cg.shared.global [%0], [%1], 16;" :: "r"(dst), "l"(src));
}
__device__ __forceinline__ void cp_commit() {
    asm volatile("cp.async.commit_group;" ::: "memory");
}

// ---------------------------------------------------------------------------
// split kernels: f32 -> bf16 hi/lo
// ---------------------------------------------------------------------------
__global__ void split_kernel(const float* __restrict__ src,
                             __nv_bfloat16* __restrict__ hi,
                             __nv_bfloat16* __restrict__ lo,
                             int n4, float scale)
{
    int i = blockIdx.x * blockDim.x + threadIdx.x;
    if (i >= n4) return;
    float4 v = ((const float4*)src)[i];
    uint32_t h0, l0, h1, l1;
    split2(v.x * scale, v.y * scale, h0, l0);
    split2(v.z * scale, v.w * scale, h1, l1);
    ((uint2*)hi)[i] = make_uint2(h0, h1);
    ((uint2*)lo)[i] = make_uint2(l0, l1);
}

__global__ void split4_kernel(const float* __restrict__ w0,
                              const float* __restrict__ w1,
                              const float* __restrict__ w2,
                              const float* __restrict__ w3,
                              __nv_bfloat16* __restrict__ hi,
                              __nv_bfloat16* __restrict__ lo, int n4)
{
    int i = blockIdx.x * blockDim.x + threadIdx.x;
    if (i >= n4) return;
    int y = blockIdx.y;
    const float* src = (y == 0) ? w0 : (y == 1) ? w1 : (y == 2) ? w2 : w3;
    float scale = (y == 0) ? 0.125f : 1.0f;
    float4 v = ((const float4*)src)[i];
    uint32_t h0, l0, h1, l1;
    split2(v.x * scale, v.y * scale, h0, l0);
    split2(v.z * scale, v.w * scale, h1, l1);
    size_t o = (size_t)y * (Dq * (size_t)Dq / 4) + i;
    ((uint2*)hi)[o] = make_uint2(h0, h1);
    ((uint2*)lo)[o] = make_uint2(l0, l1);
}

// ---------------------------------------------------------------------------
// bf16x3 GEMM — the R4 measured-best shape (87 us/GEMM):
// 128x128 CTA tile, BK=32, double-buffered cp.async, 2 syncs/iter,
// warp tile 64x32 (2x4 warp grid). smem rows: 32 bf16 = 64B data,
// stride 80B (16B-aligned, conflict-free). 81920 B smem -> 2 CTAs/SM.
// __launch_bounds__(256,2) guards the 128-reg boundary (R8 lesson).
// ---------------------------------------------------------------------------
#define GST 80
#define ATB (128*GST)          // 10240 bytes per array tile
#define STAGE_B (4*ATB)        // Ah,Al,Bh,Bl = 40960
#define GEMM_SMEM (2*STAGE_B)  // 81920

__global__ void __launch_bounds__(256, 2) gemm_tc(
    const __nv_bfloat16* __restrict__ Ah, const __nv_bfloat16* __restrict__ Al,
    const __nv_bfloat16* __restrict__ Bh, const __nv_bfloat16* __restrict__ Bl,
    const float* __restrict__ bias, float bscale,
    float* __restrict__ outF,
    __nv_bfloat16* __restrict__ outH, __nv_bfloat16* __restrict__ outL,
    int writeF)
{
    extern __shared__ char smem[];
    const uint32_t sb = smem_u32(smem);
    const int tid = threadIdx.x;
    const int wid = tid >> 5, lane = tid & 31;
    const int g = lane >> 2, tig = lane & 3;
    const int q4 = lane >> 3, m8 = lane & 7;
    const int wm = wid & 1, wn = wid >> 1;
    const int m0 = blockIdx.y * 128, n0 = blockIdx.x * 128;

    // loader role: each 64-thread group owns one array
    const int grp = tid >> 6, tg = tid & 63;
    const __nv_bfloat16* msrc =
        (grp == 0) ? Ah + (size_t)m0 * Dq :
        (grp == 1) ? Al + (size_t)m0 * Dq :
        (grp == 2) ? Bh + (size_t)n0 * Dq : Bl + (size_t)n0 * Dq;
    const uint32_t aoff = grp * ATB;

    // per-lane ldmatrix bases (relative to stage base)
    const uint32_t aRel = (uint32_t)((wm*64 + ((q4&1)<<3) + m8) * GST + ((q4>>1)<<4));
    const uint32_t bRel = (uint32_t)(2*ATB + (wn*32 + ((q4>>1)<<3) + m8) * GST + ((q4&1)<<4));

    float acc[4][4][4];
#pragma unroll
    for (int i = 0; i < 4; i++)
#pragma unroll
        for (int j = 0; j < 4; j++)
#pragma unroll
            for (int r = 0; r < 4; r++) acc[i][j][r] = 0.f;

    // prefetch stage 0
    {
        const uint32_t stage = sb;
#pragma unroll
        for (int i = 0; i < 8; i++) {
            int chunk = tg + 64 * i;
            int r = chunk >> 2, c = chunk & 3;
            cp16(stage + aoff + r * GST + c * 16, msrc + (size_t)r * Dq + c * 8);
        }
        cp_commit();
    }

    for (int it = 0; it < 32; it++) {
        const int buf = it & 1;
        const uint32_t stage = sb + buf * STAGE_B;
        if (it < 31) {
            const uint32_t nstage = sb + (buf ^ 1) * STAGE_B;
            const int k0 = (it + 1) * 32;
#pragma unroll
            for (int i = 0; i < 8; i++) {
                int chunk = tg + 64 * i;
                int r = chunk >> 2, c = chunk & 3;
                cp16(nstage + aoff + r * GST + c * 16,
                     msrc + (size_t)r * Dq + k0 + c * 8);
            }
            cp_commit();
            asm volatile("cp.async.wait_group 1;" ::: "memory");
        } else {
            asm volatile("cp.async.wait_group 0;" ::: "memory");
        }
        __syncthreads();

#pragma unroll
        for (int ks = 0; ks < 2; ks++) {
            uint32_t ah[4][4], al[4][4];
#pragma unroll
            for (int i = 0; i < 4; i++) {
                ldm_x4(ah[i], stage + aRel + i * (16*GST) + ks * 32);
                ldm_x4(al[i], stage + ATB + aRel + i * (16*GST) + ks * 32);
            }
#pragma unroll
            for (int jb = 0; jb < 2; jb++) {
                uint32_t bH[4], bL[4];
                ldm_x4(bH, stage + bRel + jb * (16*GST) + ks * 32);
                ldm_x4(bL, stage + ATB + bRel + jb * (16*GST) + ks * 32);
#pragma unroll
                for (int i = 0; i < 4; i++) {
                    mma16816(acc[i][2*jb],   ah[i], bH[0], bH[1]);
                    mma16816(acc[i][2*jb],   ah[i], bL[0], bL[1]);
                    mma16816(acc[i][2*jb],   al[i], bH[0], bH[1]);
                    mma16816(acc[i][2*jb+1], ah[i], bH[2], bH[3]);
                    mma16816(acc[i][2*jb+1], ah[i], bL[2], bL[3]);
                    mma16816(acc[i][2*jb+1], al[i], bH[2], bH[3]);
                }
            }
        }
        __syncthreads();
    }

    // epilogue
#pragma unroll
    for (int j = 0; j < 4; j++) {
        int cc = n0 + wn*32 + 8*j + 2*tig;
        float b0 = bias[cc] * bscale, b1 = bias[cc + 1] * bscale;
#pragma unroll
        for (int i = 0; i < 4; i++) {
            int rr = m0 + wm*64 + 16*i + g;
            float v00 = acc[i][j][0] + b0, v01 = acc[i][j][1] + b1;
            float v10 = acc[i][j][2] + b0, v11 = acc[i][j][3] + b1;
            if (writeF) {
                *(float2*)(outF + (size_t)rr * Dq + cc) = make_float2(v00, v01);
                *(float2*)(outF + (size_t)(rr + 8) * Dq + cc) = make_float2(v10, v11);
            } else {
                uint32_t h0, l0, h1, l1;
                split2(v00, v01, h0, l0);
                split2(v10, v11, h1, l1);
                size_t i0 = ((size_t)rr * Dq + cc) >> 1;
                size_t i1 = ((size_t)(rr + 8) * Dq + cc) >> 1;
                ((uint32_t*)outH)[i0] = h0; ((uint32_t*)outL)[i0] = l0;
                ((uint32_t*)outH)[i1] = h1; ((uint32_t*)outL)[i1] = l1;
            }
        }
    }
}

// ---------------------------------------------------------------------------
// Flash attention — R13 measured config (~270 us), unchanged.
// bf16x3 mma.sync + ldmatrix, cp.async-pipelined KV, no-max softmax
// (scores bounded, |s| <~ 15 << 88 expf range; shift-invariant, exact).
// 128 q-rows/CTA, 64-key tiles. K double-buffered, V single-buffered.
// ---------------------------------------------------------------------------
#define ATT_QH 0
#define ATT_QL 18432
#define ATT_K0 36864          // K slot s: hi +s*18432, lo +s*18432+9216
#define ATT_V  73728          // hi +0, lo +9216
#define ATT_SMEM 92160

__global__ void __launch_bounds__(256, 2) attn_kernel(
    const __nv_bfloat16* __restrict__ Qh, const __nv_bfloat16* __restrict__ Ql,
    const __nv_bfloat16* __restrict__ Kh, const __nv_bfloat16* __restrict__ Kl,
    const __nv_bfloat16* __restrict__ Vh, const __nv_bfloat16* __restrict__ Vl,
    const float* __restrict__ mask,
    __nv_bfloat16* __restrict__ Ch, __nv_bfloat16* __restrict__ Cl)
{
    extern __shared__ char smem[];
    const uint32_t sbB = smem_u32(smem);

    const int tid = threadIdx.x;
    const int lane = tid & 31;
    const int wid = tid >> 5;
    const int g = lane >> 2, tig = lane & 3;
    const int bh = blockIdx.y;
    const int b = bh >> 4, h = bh & 15;
    const int q0 = blockIdx.x * 128;

    const size_t baseQ  = ((size_t)(b * Sq + q0)) * Dq + h * HDq;
    const size_t baseKV = ((size_t)(b * Sq)) * Dq + h * HDq;

    const int q4 = lane >> 3, m8 = lane & 7;
    const uint32_t aHb = sbB + ATT_QH + (16*wid + ((q4&1)<<3) + m8)*144 + ((q4>>1)<<4);
    const uint32_t aLb = aHb + (ATT_QL - ATT_QH);
    const uint32_t kRel = (((q4>>1)<<3) + m8)*144 + ((q4&1)<<4);
    const uint32_t vHb = sbB + ATT_V + (((q4&1)<<3) + m8)*144 + ((q4>>1)<<4);
    const uint32_t vLb = vHb + 9216;

    const int hg = tid >> 7, ht = tid & 127;
    const __nv_bfloat16* ksrc = hg ? Kl : Kh;
    const __nv_bfloat16* vsrc = hg ? Vl : Vh;
    const uint32_t hoff = hg * 9216;

    // ---- load Q tile (hi/lo), natural rows ----
    {
        const __nv_bfloat16* src = hg ? Ql : Qh;
        const uint32_t off = hg ? ATT_QL : ATT_QH;
#pragma unroll
        for (int i = 0; i < 8; i++) {
            int chunk = ht + 128 * i;
            int r = chunk >> 3, c = chunk & 7;
            uint4 v = ((const uint4*)(src + baseQ + (size_t)r * Dq))[c];
            *(uint4*)(smem + off + r * 144 + c * 16) = v;
        }
    }

    // preload K tile 0
#pragma unroll
    for (int i = 0; i < 4; i++) {
        int chunk = ht + 128 * i;
        int r = chunk >> 3, c = chunk & 7;
        cp16(sbB + ATT_K0 + hoff + r * 144 + c * 16,
             ksrc + baseKV + (size_t)r * Dq + c * 8);
    }
    cp_commit();

    float l0 = 0.f, l1 = 0.f;
    float o[8][4];
#pragma unroll
    for (int jj = 0; jj < 8; jj++)
#pragma unroll
        for (int r = 0; r < 4; r++) o[jj][r] = 0.f;

    for (int t = 0; t < 32; t++) {
        const int k0 = t * 64;
        asm volatile("cp.async.wait_group 0;" ::: "memory");  // K(t) landed
        __syncthreads();                                      // + PV(t-1) done

        // issue V(t) (completes behind QK+softmax)
#pragma unroll
        for (int i = 0; i < 4; i++) {
            int chunk = ht + 128 * i;
            int r = chunk >> 3, c = chunk & 7;
            cp16(sbB + ATT_V + hoff + r * 144 + c * 16,
                 vsrc + baseKV + (size_t)(k0 + r) * Dq + c * 8);
        }
        cp_commit();

        // mask into registers (hidden behind QK)
        float2 mreg[8];
        {
            const float2* mp = (const float2*)(mask + b * Sq + k0);
#pragma unroll
            for (int j = 0; j < 8; j++) mreg[j] = mp[4*j + tig];
        }

        // ---- S = Q K^T ----
        const uint32_t kHb = sbB + ATT_K0 + (t & 1) * 18432 + kRel;
        const uint32_t kLb = kHb + 9216;
        float s[8][4];
#pragma unroll
        for (int j = 0; j < 8; j++)
#pragma unroll
            for (int r = 0; r < 4; r++) s[j][r] = 0.f;

#pragma unroll
        for (int kb = 0; kb < 4; kb++) {
            uint32_t aH[4], aL[4];
            ldm_x4(aH, aHb + kb * 32);
            ldm_x4(aL, aLb + kb * 32);
#pragma unroll
            for (int jp = 0; jp < 4; jp++) {
                uint32_t bH[4], bL[4];
                ldm_x4(bH, kHb + jp * 2304 + kb * 32);
                ldm_x4(bL, kLb + jp * 2304 + kb * 32);
                mma16816(s[2*jp],   aH, bH[0], bH[1]);
                mma16816(s[2*jp],   aH, bL[0], bL[1]);
                mma16816(s[2*jp],   aL, bH[0], bH[1]);
                mma16816(s[2*jp+1], aH, bH[2], bH[3]);
                mma16816(s[2*jp+1], aH, bL[2], bL[3]);
                mma16816(s[2*jp+1], aL, bH[2], bH[3]);
            }
        }

        // issue K(t+1) (completes behind softmax+PV)
        if (t < 31) {
            const uint32_t kdst = sbB + ATT_K0 + ((t + 1) & 1) * 18432 + hoff;
#pragma unroll
            for (int i = 0; i < 4; i++) {
                int chunk = ht + 128 * i;
                int r = chunk >> 3, c = chunk & 7;
                cp16(kdst + r * 144 + c * 16,
                     ksrc + baseKV + (size_t)(k0 + 64 + r) * Dq + c * 8);
            }
            cp_commit();
        }

        // ---- softmax (no max subtraction; exact for bounded scores) ----
        float sum0 = 0.f, sum1 = 0.f;
#pragma unroll
        for (int j = 0; j < 8; j++) {
            s[j][0] = __expf(s[j][0] + mreg[j].x); sum0 += s[j][0];
            s[j][1] = __expf(s[j][1] + mreg[j].y); sum0 += s[j][1];
            s[j][2] = __expf(s[j][2] + mreg[j].x); sum1 += s[j][2];
            s[j][3] = __expf(s[j][3] + mreg[j].y); sum1 += s[j][3];
        }
        sum0 += __shfl_xor_sync(0xffffffffu, sum0, 1);
        sum0 += __shfl_xor_sync(0xffffffffu, sum0, 2);
        sum1 += __shfl_xor_sync(0xffffffffu, sum1, 1);
        sum1 += __shfl_xor_sync(0xffffffffu, sum1, 2);
        l0 += sum0;
        l1 += sum1;

        // ---- pack P as PV A-fragments (hi/lo) ----
        uint32_t ph[4][4], pl[4][4];
#pragma unroll
        for (int kb = 0; kb < 4; kb++) {
            split2(s[2*kb][0],   s[2*kb][1],   ph[kb][0], pl[kb][0]);
            split2(s[2*kb][2],   s[2*kb][3],   ph[kb][1], pl[kb][1]);
            split2(s[2*kb+1][0], s[2*kb+1][1], ph[kb][2], pl[kb][2]);
            split2(s[2*kb+1][2], s[2*kb+1][3], ph[kb][3], pl[kb][3]);
        }

        // V(t) done (K(t+1) may still be in flight)
        if (t < 31) asm volatile("cp.async.wait_group 1;" ::: "memory");
        else        asm volatile("cp.async.wait_group 0;" ::: "memory");
        __syncthreads();

        // ---- O += P V ----
#pragma unroll
        for (int kb = 0; kb < 4; kb++) {
#pragma unroll
            for (int jp = 0; jp < 4; jp++) {
                uint32_t vH[4], vL[4];
                ldm_x4_t(vH, vHb + kb * 2304 + jp * 32);
                ldm_x4_t(vL, vLb + kb * 2304 + jp * 32);
                mma16816(o[2*jp],   ph[kb], vH[0], vH[1]);
                mma16816(o[2*jp],   ph[kb], vL[0], vL[1]);
                mma16816(o[2*jp],   pl[kb], vH[0], vH[1]);
                mma16816(o[2*jp+1], ph[kb], vH[2], vH[3]);
                mma16816(o[2*jp+1], ph[kb], vL[2], vL[3]);
                mma16816(o[2*jp+1], pl[kb], vH[2], vH[3]);
            }
        }
    }

    // ---- epilogue: ctx as bf16 hi/lo ----
    float inv0 = 1.0f / l0, inv1 = 1.0f / l1;
    size_t row0 = (size_t)(b * Sq + q0 + 16*wid + g);
#pragma unroll
    for (int jj = 0; jj < 8; jj++) {
        int cc = 8*jj + 2*tig;
        uint32_t h0, l0b, h1, l1b;
        split2(o[jj][0] * inv0, o[jj][1] * inv0, h0, l0b);
        split2(o[jj][2] * inv1, o[jj][3] * inv1, h1, l1b);
        size_t i0 = (row0 * Dq + h * HDq + cc) >> 1;
        size_t i1 = ((row0 + 8) * Dq + h * HDq + cc) >> 1;
        ((uint32_t*)Ch)[i0] = h0; ((uint32_t*)Cl)[i0] = l0b;
        ((uint32_t*)Ch)[i1] = h1; ((uint32_t*)Cl)[i1] = l1b;
    }
}

// ---------------------------------------------------------------------------

extern "C" void kernel_launch(void* const* d_in, const int* in_sizes, int n_in,
                              void* d_out, int out_size)
{
    const float* hs   = (const float*)d_in[0];
    const float* mask = (const float*)d_in[1];
    const float* Wq   = (const float*)d_in[2];
    const float* bq   = (const float*)d_in[3];
    const float* Wk   = (const float*)d_in[4];
    const float* bk   = (const float*)d_in[5];
    const float* Wv   = (const float*)d_in[6];
    const float* bv   = (const float*)d_in[7];
    const float* Wo   = (const float*)d_in[8];
    const float* bo   = (const float*)d_in[9];
    float* out = (float*)d_out;

    __nv_bfloat16 *xh, *xl, *wh, *wl, *qh, *ql, *kh, *kl, *vh, *vl, *ch, *cl;
    cudaGetSymbolAddress((void**)&xh, gXh); cudaGetSymbolAddress((void**)&xl, gXl);
    cudaGetSymbolAddress((void**)&wh, gWh); cudaGetSymbolAddress((void**)&wl, gWl);
    cudaGetSymbolAddress((void**)&qh, gQh); cudaGetSymbolAddress((void**)&ql, gQl);
    cudaGetSymbolAddress((void**)&kh, gKh); cudaGetSymbolAddress((void**)&kl, gKl);
    cudaGetSymbolAddress((void**)&vh, gVh); cudaGetSymbolAddress((void**)&vl, gVl);
    cudaGetSymbolAddress((void**)&ch, gCh); cudaGetSymbolAddress((void**)&cl, gCl);

    const int WN = Dq * Dq;

    split_kernel<<<(Mq*Dq/4 + 255)/256, 256>>>(hs, xh, xl, Mq*Dq/4, 1.0f);
    dim3 sgrid((WN/4 + 255)/256, 4);
    split4_kernel<<<sgrid, 256>>>(Wq, Wk, Wv, Wo, wh, wl, WN/4);

    cudaFuncSetAttribute(gemm_tc, cudaFuncAttributeMaxDynamicSharedMemorySize, GEMM_SMEM);
    dim3 ggrid(Dq / 128, Mq / 128);

    gemm_tc<<<ggrid, 256, GEMM_SMEM>>>(xh, xl, wh + 0*WN, wl + 0*WN, bq, 0.125f,
                                       nullptr, qh, ql, 0);
    gemm_tc<<<ggrid, 256, GEMM_SMEM>>>(xh, xl, wh + 1*WN, wl + 1*WN, bk, 1.0f,
                                       nullptr, kh, kl, 0);
    gemm_tc<<<ggrid, 256, GEMM_SMEM>>>(xh, xl, wh + 2*WN, wl + 2*WN, bv, 1.0f,
                                       nullptr, vh, vl, 0);

    cudaFuncSetAttribute(attn_kernel, cudaFuncAttributeMaxDynamicSharedMemorySize, ATT_SMEM);
    dim3 agrid(Sq / 128, Bq * Hq);
    attn_kernel<<<agrid, 256, ATT_SMEM>>>(qh, ql, kh, kl, vh, vl, mask, ch, cl);

    gemm_tc<<<ggrid, 256, GEMM_SMEM>>>(ch, cl, wh + 3*WN, wl + 3*WN, bo, 1.0f,
                                       out, nullptr, nullptr, 1);
}

// round 15
// speedup vs baseline: 1.2147x; 1.0264x over previous
#include <cuda_runtime.h>
#include <cuda_bf16.h>
#include <cstdint>

#define Bq 2
#define Sq 2048
#define Dq 1024
#define Hq 16
#define HDq 64
#define Mq (Bq*Sq)

// ---------------- global scratch (allocation-free) ----------------
__device__ __align__(16) __nv_bfloat16 gXh[Mq*Dq], gXl[Mq*Dq];
__device__ __align__(16) __nv_bfloat16 gWh[4][Dq*Dq], gWl[4][Dq*Dq];
__device__ __align__(16) __nv_bfloat16 gQh[Mq*Dq], gQl[Mq*Dq];
__device__ __align__(16) __nv_bfloat16 gKh[Mq*Dq], gKl[Mq*Dq];
__device__ __align__(16) __nv_bfloat16 gVh[Mq*Dq], gVl[Mq*Dq];
__device__ __align__(16) __nv_bfloat16 gCh[Mq*Dq], gCl[Mq*Dq];

// ---------------- small helpers ----------------
__device__ __forceinline__ void split2(float x, float y,
                                       uint32_t& hi, uint32_t& lo) {
    __nv_bfloat16 hx = __float2bfloat16_rn(x);
    __nv_bfloat16 hy = __float2bfloat16_rn(y);
    __nv_bfloat162 h2 = __halves2bfloat162(hx, hy);
    __nv_bfloat162 l2 = __halves2bfloat162(
        __float2bfloat16_rn(x - __bfloat162float(hx)),
        __float2bfloat16_rn(y - __bfloat162float(hy)));
    hi = *reinterpret_cast<uint32_t*>(&h2);
    lo = *reinterpret_cast<uint32_t*>(&l2);
}

__device__ __forceinline__ void mma16816(float* c, const uint32_t* a,
                                         uint32_t b0, uint32_t b1) {
    asm volatile("mma.sync.aligned.m16n8k16.row.col.f32.bf16.bf16.f32 "
                 "{%0,%1,%2,%3}, {%4,%5,%6,%7}, {%8,%9}, {%0,%1,%2,%3};"
                 : "+f"(c[0]), "+f"(c[1]), "+f"(c[2]), "+f"(c[3])
                 : "r"(a[0]), "r"(a[1]), "r"(a[2]), "r"(a[3]),
                   "r"(b0), "r"(b1));
}

__device__ __forceinline__ void ldm_x4(uint32_t* r, uint32_t a) {
    asm volatile("ldmatrix.sync.aligned.m8n8.x4.shared.b16 {%0,%1,%2,%3}, [%4];"
                 : "=r"(r[0]), "=r"(r[1]), "=r"(r[2]), "=r"(r[3]) : "r"(a));
}
__device__ __forceinline__ void ldm_x4_t(uint32_t* r, uint32_t a) {
    asm volatile("ldmatrix.sync.aligned.m8n8.x4.trans.shared.b16 {%0,%1,%2,%3}, [%4];"
                 : "=r"(r[0]), "=r"(r[1]), "=r"(r[2]), "=r"(r[3]) : "r"(a));
}

__device__ __forceinline__ uint32_t smem_u32(const void* p) {
    uint32_t a;
    asm("{ .reg .u64 t; cvta.to.shared.u64 t, %1; cvt.u32.u64 %0, t; }"
        : "=r"(a) : "l"(p));
    return a;
}

__device__ __forceinline__ void cp16(uint32_t dst, const void* src) {
    asm volatile("cp.async.cg.shared.global [%0], [%1], 16;" :: "r"(dst), "l"(src));
}
__device__ __forceinline__ void cp_commit() {
    asm volatile("cp.async.commit_group;" ::: "memory");
}

// ---------------------------------------------------------------------------
// split kernels: f32 -> bf16 hi/lo
// ---------------------------------------------------------------------------
__global__ void split_kernel(const float* __restrict__ src,
                             __nv_bfloat16* __restrict__ hi,
                             __nv_bfloat16* __restrict__ lo,
                             int n4, float scale)
{
    int i = blockIdx.x * blockDim.x + threadIdx.x;
    if (i >= n4) return;
    float4 v = ((const float4*)src)[i];
    uint32_t h0, l0, h1, l1;
    split2(v.x * scale, v.y * scale, h0, l0);
    split2(v.z * scale, v.w * scale, h1, l1);
    ((uint2*)hi)[i] = make_uint2(h0, h1);
    ((uint2*)lo)[i] = make_uint2(l0, l1);
}

__global__ void split4_kernel(const float* __restrict__ w0,
                              const float* __restrict__ w1,
                              const float* __restrict__ w2,
                              const float* __restrict__ w3,
                              __nv_bfloat16* __restrict__ hi,
                              __nv_bfloat16* __restrict__ lo, int n4)
{
    int i = blockIdx.x * blockDim.x + threadIdx.x;
    if (i >= n4) return;
    int y = blockIdx.y;
    const float* src = (y == 0) ? w0 : (y == 1) ? w1 : (y == 2) ? w2 : w3;
    float scale = (y == 0) ? 0.125f : 1.0f;
    float4 v = ((const float4*)src)[i];
    uint32_t h0, l0, h1, l1;
    split2(v.x * scale, v.y * scale, h0, l0);
    split2(v.z * scale, v.w * scale, h1, l1);
    size_t o = (size_t)y * (Dq * (size_t)Dq / 4) + i;
    ((uint2*)hi)[o] = make_uint2(h0, h1);
    ((uint2*)lo)[o] = make_uint2(l0, l1);
}

// ---------------------------------------------------------------------------
// bf16x3 GEMM core (R4/R14 measured-best shape, ~93.5 us at issue floor):
// 128x128 CTA tile, BK=32, double-buffered cp.async, warp tile 64x32.
// smem rows: 32 bf16 = 64B data, stride 80B. 81920 B smem -> 2 CTAs/SM.
// ---------------------------------------------------------------------------
#define GST 80
#define ATB (128*GST)          // 10240 bytes per array tile
#define STAGE_B (4*ATB)        // Ah,Al,Bh,Bl = 40960
#define GEMM_SMEM (2*STAGE_B)  // 81920

// Shared mainloop body: computes acc for this CTA tile.
__device__ __forceinline__ void gemm_mainloop(
    uint32_t sb, int tid,
    const __nv_bfloat16* __restrict__ Ah, const __nv_bfloat16* __restrict__ Al,
    const __nv_bfloat16* __restrict__ Bh, const __nv_bfloat16* __restrict__ Bl,
    int m0, int n0, float acc[4][4][4])
{
    const int lane = tid & 31;
    const int q4 = lane >> 3, m8 = lane & 7;
    const int wid = tid >> 5;
    const int wm = wid & 1, wn = wid >> 1;

    const int grp = tid >> 6, tg = tid & 63;
    const __nv_bfloat16* msrc =
        (grp == 0) ? Ah + (size_t)m0 * Dq :
        (grp == 1) ? Al + (size_t)m0 * Dq :
        (grp == 2) ? Bh + (size_t)n0 * Dq : Bl + (size_t)n0 * Dq;
    const uint32_t aoff = grp * ATB;

    const uint32_t aRel = (uint32_t)((wm*64 + ((q4&1)<<3) + m8) * GST + ((q4>>1)<<4));
    const uint32_t bRel = (uint32_t)(2*ATB + (wn*32 + ((q4>>1)<<3) + m8) * GST + ((q4&1)<<4));

    // prefetch stage 0
    {
#pragma unroll
        for (int i = 0; i < 8; i++) {
            int chunk = tg + 64 * i;
            int r = chunk >> 2, c = chunk & 3;
            cp16(sb + aoff + r * GST + c * 16, msrc + (size_t)r * Dq + c * 8);
        }
        cp_commit();
    }

    for (int it = 0; it < 32; it++) {
        const int buf = it & 1;
        const uint32_t stage = sb + buf * STAGE_B;
        if (it < 31) {
            const uint32_t nstage = sb + (buf ^ 1) * STAGE_B;
            const int k0 = (it + 1) * 32;
#pragma unroll
            for (int i = 0; i < 8; i++) {
                int chunk = tg + 64 * i;
                int r = chunk >> 2, c = chunk & 3;
                cp16(nstage + aoff + r * GST + c * 16,
                     msrc + (size_t)r * Dq + k0 + c * 8);
            }
            cp_commit();
            asm volatile("cp.async.wait_group 1;" ::: "memory");
        } else {
            asm volatile("cp.async.wait_group 0;" ::: "memory");
        }
        __syncthreads();

#pragma unroll
        for (int ks = 0; ks < 2; ks++) {
            uint32_t ah[4][4], al[4][4];
#pragma unroll
            for (int i = 0; i < 4; i++) {
                ldm_x4(ah[i], stage + aRel + i * (16*GST) + ks * 32);
                ldm_x4(al[i], stage + ATB + aRel + i * (16*GST) + ks * 32);
            }
#pragma unroll
            for (int jb = 0; jb < 2; jb++) {
                uint32_t bH[4], bL[4];
                ldm_x4(bH, stage + bRel + jb * (16*GST) + ks * 32);
                ldm_x4(bL, stage + ATB + bRel + jb * (16*GST) + ks * 32);
#pragma unroll
                for (int i = 0; i < 4; i++) {
                    mma16816(acc[i][2*jb],   ah[i], bH[0], bH[1]);
                    mma16816(acc[i][2*jb],   ah[i], bL[0], bL[1]);
                    mma16816(acc[i][2*jb],   al[i], bH[0], bH[1]);
                    mma16816(acc[i][2*jb+1], ah[i], bH[2], bH[3]);
                    mma16816(acc[i][2*jb+1], ah[i], bL[2], bL[3]);
                    mma16816(acc[i][2*jb+1], al[i], bH[2], bH[3]);
                }
            }
        }
        __syncthreads();
    }
}

// Fused QKV: grid.z selects {Wq,Wk,Wv}; outputs bf16 hi/lo.
__global__ void __launch_bounds__(256, 2) gemm_qkv(
    const __nv_bfloat16* __restrict__ Xh, const __nv_bfloat16* __restrict__ Xl,
    const __nv_bfloat16* __restrict__ WhB, const __nv_bfloat16* __restrict__ WlB,
    const float* __restrict__ bq, const float* __restrict__ bk,
    const float* __restrict__ bv,
    __nv_bfloat16* __restrict__ Qh, __nv_bfloat16* __restrict__ Ql,
    __nv_bfloat16* __restrict__ Kh, __nv_bfloat16* __restrict__ Kl,
    __nv_bfloat16* __restrict__ Vh, __nv_bfloat16* __restrict__ Vl)
{
    extern __shared__ char smem[];
    const uint32_t sb = smem_u32(smem);
    const int tid = threadIdx.x;
    const int z = blockIdx.z;
    const int m0 = blockIdx.y * 128, n0 = blockIdx.x * 128;
    const size_t WN = (size_t)Dq * Dq;

    const __nv_bfloat16* Bh = WhB + (size_t)z * WN;
    const __nv_bfloat16* Bl = WlB + (size_t)z * WN;
    const float* bias = (z == 0) ? bq : (z == 1) ? bk : bv;
    const float bscale = (z == 0) ? 0.125f : 1.0f;
    __nv_bfloat16* outH = (z == 0) ? Qh : (z == 1) ? Kh : Vh;
    __nv_bfloat16* outL = (z == 0) ? Ql : (z == 1) ? Kl : Vl;

    float acc[4][4][4];
#pragma unroll
    for (int i = 0; i < 4; i++)
#pragma unroll
        for (int j = 0; j < 4; j++)
#pragma unroll
            for (int r = 0; r < 4; r++) acc[i][j][r] = 0.f;

    gemm_mainloop(sb, tid, Xh, Xl, Bh, Bl, m0, n0, acc);

    const int lane = tid & 31, wid = tid >> 5;
    const int g = lane >> 2, tig = lane & 3;
    const int wm = wid & 1, wn = wid >> 1;
#pragma unroll
    for (int j = 0; j < 4; j++) {
        int cc = n0 + wn*32 + 8*j + 2*tig;
        float b0 = bias[cc] * bscale, b1 = bias[cc + 1] * bscale;
#pragma unroll
        for (int i = 0; i < 4; i++) {
            int rr = m0 + wm*64 + 16*i + g;
            uint32_t h0, l0, h1, l1;
            split2(acc[i][j][0] + b0, acc[i][j][1] + b1, h0, l0);
            split2(acc[i][j][2] + b0, acc[i][j][3] + b1, h1, l1);
            size_t i0 = ((size_t)rr * Dq + cc) >> 1;
            size_t i1 = ((size_t)(rr + 8) * Dq + cc) >> 1;
            ((uint32_t*)outH)[i0] = h0; ((uint32_t*)outL)[i0] = l0;
            ((uint32_t*)outH)[i1] = h1; ((uint32_t*)outL)[i1] = l1;
        }
    }
}

// Output projection: f32 out.
__global__ void __launch_bounds__(256, 2) gemm_out(
    const __nv_bfloat16* __restrict__ Ah, const __nv_bfloat16* __restrict__ Al,
    const __nv_bfloat16* __restrict__ Bh, const __nv_bfloat16* __restrict__ Bl,
    const float* __restrict__ bias, float* __restrict__ outF)
{
    extern __shared__ char smem[];
    const uint32_t sb = smem_u32(smem);
    const int tid = threadIdx.x;
    const int m0 = blockIdx.y * 128, n0 = blockIdx.x * 128;

    float acc[4][4][4];
#pragma unroll
    for (int i = 0; i < 4; i++)
#pragma unroll
        for (int j = 0; j < 4; j++)
#pragma unroll
            for (int r = 0; r < 4; r++) acc[i][j][r] = 0.f;

    gemm_mainloop(sb, tid, Ah, Al, Bh, Bl, m0, n0, acc);

    const int lane = tid & 31, wid = tid >> 5;
    const int g = lane >> 2, tig = lane & 3;
    const int wm = wid & 1, wn = wid >> 1;
#pragma unroll
    for (int j = 0; j < 4; j++) {
        int cc = n0 + wn*32 + 8*j + 2*tig;
        float b0 = bias[cc], b1 = bias[cc + 1];
#pragma unroll
        for (int i = 0; i < 4; i++) {
            int rr = m0 + wm*64 + 16*i + g;
            *(float2*)(outF + (size_t)rr * Dq + cc) =
                make_float2(acc[i][j][0] + b0, acc[i][j][1] + b1);
            *(float2*)(outF + (size_t)(rr + 8) * Dq + cc) =
                make_float2(acc[i][j][2] + b0, acc[i][j][3] + b1);
        }
    }
}

// ---------------------------------------------------------------------------
// Flash attention: bf16x3 mma.sync + ldmatrix, K AND V double-buffered ->
// ONE __syncthreads + ONE wait per tile. No-max softmax (scores bounded,
// shift-invariant => exact). 128 q-rows/CTA, 64-key tiles.
// smem: Q 36864 + K 2x18432 + V 2x18432 = 110592 B -> 2 CTAs/SM.
// ---------------------------------------------------------------------------
#define ATT_QH 0
#define ATT_QL 18432
#define ATT_K0 36864          // K slot s at +s*18432 (hi +0, lo +9216)
#define ATT_V0 73728          // V slot s at +s*18432 (hi +0, lo +9216)
#define ATT_SMEM 110592

__global__ void __launch_bounds__(256, 2) attn_kernel(
    const __nv_bfloat16* __restrict__ Qh, const __nv_bfloat16* __restrict__ Ql,
    const __nv_bfloat16* __restrict__ Kh, const __nv_bfloat16* __restrict__ Kl,
    const __nv_bfloat16* __restrict__ Vh, const __nv_bfloat16* __restrict__ Vl,
    const float* __restrict__ mask,
    __nv_bfloat16* __restrict__ Ch, __nv_bfloat16* __restrict__ Cl)
{
    extern __shared__ char smem[];
    const uint32_t sbB = smem_u32(smem);

    const int tid = threadIdx.x;
    const int lane = tid & 31;
    const int wid = tid >> 5;
    const int g = lane >> 2, tig = lane & 3;
    const int bh = blockIdx.y;
    const int b = bh >> 4, h = bh & 15;
    const int q0 = blockIdx.x * 128;

    const size_t baseQ  = ((size_t)(b * Sq + q0)) * Dq + h * HDq;
    const size_t baseKV = ((size_t)(b * Sq)) * Dq + h * HDq;

    const int q4 = lane >> 3, m8 = lane & 7;
    const uint32_t aHb = sbB + ATT_QH + (16*wid + ((q4&1)<<3) + m8)*144 + ((q4>>1)<<4);
    const uint32_t aLb = aHb + (ATT_QL - ATT_QH);
    const uint32_t kRel = (((q4>>1)<<3) + m8)*144 + ((q4&1)<<4);
    const uint32_t vRel = (((q4&1)<<3) + m8)*144 + ((q4>>1)<<4);

    const int hg = tid >> 7, ht = tid & 127;
    const __nv_bfloat16* ksrc = hg ? Kl : Kh;
    const __nv_bfloat16* vsrc = hg ? Vl : Vh;
    const uint32_t hoff = hg * 9216;

    // ---- load Q tile (hi/lo), natural rows ----
    {
        const __nv_bfloat16* src = hg ? Ql : Qh;
        const uint32_t off = hg ? ATT_QL : ATT_QH;
#pragma unroll
        for (int i = 0; i < 8; i++) {
            int chunk = ht + 128 * i;
            int r = chunk >> 3, c = chunk & 7;
            uint4 v = ((const uint4*)(src + baseQ + (size_t)r * Dq))[c];
            *(uint4*)(smem + off + r * 144 + c * 16) = v;
        }
    }

    // preload K0 + V0 into slot 0 (one commit group)
#pragma unroll
    for (int i = 0; i < 4; i++) {
        int chunk = ht + 128 * i;
        int r = chunk >> 3, c = chunk & 7;
        cp16(sbB + ATT_K0 + hoff + r * 144 + c * 16,
             ksrc + baseKV + (size_t)r * Dq + c * 8);
        cp16(sbB + ATT_V0 + hoff + r * 144 + c * 16,
             vsrc + baseKV + (size_t)r * Dq + c * 8);
    }
    cp_commit();

    float l0 = 0.f, l1 = 0.f;
    float o[8][4];
#pragma unroll
    for (int jj = 0; jj < 8; jj++)
#pragma unroll
        for (int r = 0; r < 4; r++) o[jj][r] = 0.f;

    for (int t = 0; t < 32; t++) {
        const int k0 = t * 64;
        const uint32_t slot = (t & 1) * 18432;

        // K(t)+V(t) landed; all warps done with the other slot (read in t-1)
        asm volatile("cp.async.wait_group 0;" ::: "memory");
        __syncthreads();

        // mask into registers (hidden behind QK)
        float2 mreg[8];
        {
            const float2* mp = (const float2*)(mask + b * Sq + k0);
#pragma unroll
            for (int j = 0; j < 8; j++) mreg[j] = mp[4*j + tig];
        }

        // ---- S = Q K^T ----
        const uint32_t kHb = sbB + ATT_K0 + slot + kRel;
        const uint32_t kLb = kHb + 9216;
        float s[8][4];
#pragma unroll
        for (int j = 0; j < 8; j++)
#pragma unroll
            for (int r = 0; r < 4; r++) s[j][r] = 0.f;

#pragma unroll
        for (int kb = 0; kb < 4; kb++) {
            uint32_t aH[4], aL[4];
            ldm_x4(aH, aHb + kb * 32);
            ldm_x4(aL, aLb + kb * 32);
#pragma unroll
            for (int jp = 0; jp < 4; jp++) {
                uint32_t bH[4], bL[4];
                ldm_x4(bH, kHb + jp * 2304 + kb * 32);
                ldm_x4(bL, kLb + jp * 2304 + kb * 32);
                mma16816(s[2*jp],   aH, bH[0], bH[1]);
                mma16816(s[2*jp],   aH, bL[0], bL[1]);
                mma16816(s[2*jp],   aL, bH[0], bH[1]);
                mma16816(s[2*jp+1], aH, bH[2], bH[3]);
                mma16816(s[2*jp+1], aH, bL[2], bL[3]);
                mma16816(s[2*jp+1], aL, bH[2], bH[3]);
            }
        }

        // issue K(t+1)+V(t+1) into the other slot (safe: last read in t-1,
        // fenced by this tile's top barrier)
        if (t < 31) {
            const uint32_t nslot = ((t + 1) & 1) * 18432;
#pragma unroll
            for (int i = 0; i < 4; i++) {
                int chunk = ht + 128 * i;
                int r = chunk >> 3, c = chunk & 7;
                cp16(sbB + ATT_K0 + nslot + hoff + r * 144 + c * 16,
                     ksrc + baseKV + (size_t)(k0 + 64 + r) * Dq + c * 8);
                cp16(sbB + ATT_V0 + nslot + hoff + r * 144 + c * 16,
                     vsrc + baseKV + (size_t)(k0 + 64 + r) * Dq + c * 8);
            }
            cp_commit();
        }

        // ---- softmax (no max subtraction; exact for bounded scores) ----
        float sum0 = 0.f, sum1 = 0.f;
#pragma unroll
        for (int j = 0; j < 8; j++) {
            s[j][0] = __expf(s[j][0] + mreg[j].x); sum0 += s[j][0];
            s[j][1] = __expf(s[j][1] + mreg[j].y); sum0 += s[j][1];
            s[j][2] = __expf(s[j][2] + mreg[j].x); sum1 += s[j][2];
            s[j][3] = __expf(s[j][3] + mreg[j].y); sum1 += s[j][3];
        }
        sum0 += __shfl_xor_sync(0xffffffffu, sum0, 1);
        sum0 += __shfl_xor_sync(0xffffffffu, sum0, 2);
        sum1 += __shfl_xor_sync(0xffffffffu, sum1, 1);
        sum1 += __shfl_xor_sync(0xffffffffu, sum1, 2);
        l0 += sum0;
        l1 += sum1;

        // ---- pack P as PV A-fragments (hi/lo) ----
        uint32_t ph[4][4], pl[4][4];
#pragma unroll
        for (int kb = 0; kb < 4; kb++) {
            split2(s[2*kb][0],   s[2*kb][1],   ph[kb][0], pl[kb][0]);
            split2(s[2*kb][2],   s[2*kb][3],   ph[kb][1], pl[kb][1]);
            split2(s[2*kb+1][0], s[2*kb+1][1], ph[kb][2], pl[kb][2]);
            split2(s[2*kb+1][2], s[2*kb+1][3], ph[kb][3], pl[kb][3]);
        }

        // ---- O += P V  (V slot t&1; no extra barrier needed) ----
        const uint32_t vHb = sbB + ATT_V0 + slot + vRel;
        const uint32_t vLb = vHb + 9216;
#pragma unroll
        for (int kb = 0; kb < 4; kb++) {
#pragma unroll
            for (int jp = 0; jp < 4; jp++) {
                uint32_t vH[4], vL[4];
                ldm_x4_t(vH, vHb + kb * 2304 + jp * 32);
                ldm_x4_t(vL, vLb + kb * 2304 + jp * 32);
                mma16816(o[2*jp],   ph[kb], vH[0], vH[1]);
                mma16816(o[2*jp],   ph[kb], vL[0], vL[1]);
                mma16816(o[2*jp],   pl[kb], vH[0], vH[1]);
                mma16816(o[2*jp+1], ph[kb], vH[2], vH[3]);
                mma16816(o[2*jp+1], ph[kb], vL[2], vL[3]);
                mma16816(o[2*jp+1], pl[kb], vH[2], vH[3]);
            }
        }
    }

    // ---- epilogue: ctx as bf16 hi/lo ----
    float inv0 = 1.0f / l0, inv1 = 1.0f / l1;
    size_t row0 = (size_t)(b * Sq + q0 + 16*wid + g);
#pragma unroll
    for (int jj = 0; jj < 8; jj++) {
        int cc = 8*jj + 2*tig;
        uint32_t h0, l0b, h1, l1b;
        split2(o[jj][0] * inv0, o[jj][1] * inv0, h0, l0b);
        split2(o[jj][2] * inv1, o[jj][3] * inv1, h1, l1b);
        size_t i0 = (row0 * Dq + h * HDq + cc) >> 1;
        size_t i1 = ((row0 + 8) * Dq + h * HDq + cc) >> 1;
        ((uint32_t*)Ch)[i0] = h0; ((uint32_t*)Cl)[i0] = l0b;
        ((uint32_t*)Ch)[i1] = h1; ((uint32_t*)Cl)[i1] = l1b;
    }
}

// ---------------------------------------------------------------------------

extern "C" void kernel_launch(void* const* d_in, const int* in_sizes, int n_in,
                              void* d_out, int out_size)
{
    const float* hs   = (const float*)d_in[0];
    const float* mask = (const float*)d_in[1];
    const float* Wq   = (const float*)d_in[2];
    const float* bq   = (const float*)d_in[3];
    const float* Wk   = (const float*)d_in[4];
    const float* bk   = (const float*)d_in[5];
    const float* Wv   = (const float*)d_in[6];
    const float* bv   = (const float*)d_in[7];
    const float* Wo   = (const float*)d_in[8];
    const float* bo   = (const float*)d_in[9];
    float* out = (float*)d_out;

    __nv_bfloat16 *xh, *xl, *wh, *wl, *qh, *ql, *kh, *kl, *vh, *vl, *ch, *cl;
    cudaGetSymbolAddress((void**)&xh, gXh); cudaGetSymbolAddress((void**)&xl, gXl);
    cudaGetSymbolAddress((void**)&wh, gWh); cudaGetSymbolAddress((void**)&wl, gWl);
    cudaGetSymbolAddress((void**)&qh, gQh); cudaGetSymbolAddress((void**)&ql, gQl);
    cudaGetSymbolAddress((void**)&kh, gKh); cudaGetSymbolAddress((void**)&kl, gKl);
    cudaGetSymbolAddress((void**)&vh, gVh); cudaGetSymbolAddress((void**)&vl, gVl);
    cudaGetSymbolAddress((void**)&ch, gCh); cudaGetSymbolAddress((void**)&cl, gCl);

    const int WN = Dq * Dq;

    split_kernel<<<(Mq*Dq/4 + 255)/256, 256>>>(hs, xh, xl, Mq*Dq/4, 1.0f);
    dim3 sgrid((WN/4 + 255)/256, 4);
    split4_kernel<<<sgrid, 256>>>(Wq, Wk, Wv, Wo, wh, wl, WN/4);

    cudaFuncSetAttribute(gemm_qkv, cudaFuncAttributeMaxDynamicSharedMemorySize, GEMM_SMEM);
    cudaFuncSetAttribute(gemm_out, cudaFuncAttributeMaxDynamicSharedMemorySize, GEMM_SMEM);

    // fused QKV: one launch, grid.z selects the weight matrix
    dim3 qgrid(Dq / 128, Mq / 128, 3);
    gemm_qkv<<<qgrid, 256, GEMM_SMEM>>>(xh, xl, wh, wl, bq, bk, bv,
                                        qh, ql, kh, kl, vh, vl);

    cudaFuncSetAttribute(attn_kernel, cudaFuncAttributeMaxDynamicSharedMemorySize, ATT_SMEM);
    dim3 agrid(Sq / 128, Bq * Hq);
    attn_kernel<<<agrid, 256, ATT_SMEM>>>(qh, ql, kh, kl, vh, vl, mask, ch, cl);

    dim3 ggrid(Dq / 128, Mq / 128);
    gemm_out<<<ggrid, 256, GEMM_SMEM>>>(ch, cl, wh + 3*(size_t)WN, wl + 3*(size_t)WN,
                                        bo, out);
}

// round 16
// speedup vs baseline: 1.2260x; 1.0093x over previous
#include <cuda_runtime.h>
#include <cuda_bf16.h>
#include <cstdint>

#define Bq 2
#define Sq 2048
#define Dq 1024
#define Hq 16
#define HDq 64
#define Mq (Bq*Sq)
#define L2E 1.4426950408889634f

// ---------------- global scratch (allocation-free) ----------------
__device__ __align__(16) __nv_bfloat16 gXh[Mq*Dq], gXl[Mq*Dq];
__device__ __align__(16) __nv_bfloat16 gWh[4][Dq*Dq], gWl[4][Dq*Dq];
__device__ __align__(16) __nv_bfloat16 gQh[Mq*Dq], gQl[Mq*Dq];
__device__ __align__(16) __nv_bfloat16 gKh[Mq*Dq], gKl[Mq*Dq];
__device__ __align__(16) __nv_bfloat16 gVh[Mq*Dq], gVl[Mq*Dq];
__device__ __align__(16) __nv_bfloat16 gCh[Mq*Dq], gCl[Mq*Dq];

// ---------------- small helpers ----------------
__device__ __forceinline__ void split2(float x, float y,
                                       uint32_t& hi, uint32_t& lo) {
    __nv_bfloat16 hx = __float2bfloat16_rn(x);
    __nv_bfloat16 hy = __float2bfloat16_rn(y);
    __nv_bfloat162 h2 = __halves2bfloat162(hx, hy);
    __nv_bfloat162 l2 = __halves2bfloat162(
        __float2bfloat16_rn(x - __bfloat162float(hx)),
        __float2bfloat16_rn(y - __bfloat162float(hy)));
    hi = *reinterpret_cast<uint32_t*>(&h2);
    lo = *reinterpret_cast<uint32_t*>(&l2);
}

__device__ __forceinline__ float ex2(float x) {
    float y;
    asm("ex2.approx.f32 %0, %1;" : "=f"(y) : "f"(x));
    return y;
}

__device__ __forceinline__ void mma16816(float* c, const uint32_t* a,
                                         uint32_t b0, uint32_t b1) {
    asm volatile("mma.sync.aligned.m16n8k16.row.col.f32.bf16.bf16.f32 "
                 "{%0,%1,%2,%3}, {%4,%5,%6,%7}, {%8,%9}, {%0,%1,%2,%3};"
                 : "+f"(c[0]), "+f"(c[1]), "+f"(c[2]), "+f"(c[3])
                 : "r"(a[0]), "r"(a[1]), "r"(a[2]), "r"(a[3]),
                   "r"(b0), "r"(b1));
}

__device__ __forceinline__ void ldm_x4(uint32_t* r, uint32_t a) {
    asm volatile("ldmatrix.sync.aligned.m8n8.x4.shared.b16 {%0,%1,%2,%3}, [%4];"
                 : "=r"(r[0]), "=r"(r[1]), "=r"(r[2]), "=r"(r[3]) : "r"(a));
}
__device__ __forceinline__ void ldm_x4_t(uint32_t* r, uint32_t a) {
    asm volatile("ldmatrix.sync.aligned.m8n8.x4.trans.shared.b16 {%0,%1,%2,%3}, [%4];"
                 : "=r"(r[0]), "=r"(r[1]), "=r"(r[2]), "=r"(r[3]) : "r"(a));
}

__device__ __forceinline__ uint32_t smem_u32(const void* p) {
    uint32_t a;
    asm("{ .reg .u64 t; cvta.to.shared.u64 t, %1; cvt.u32.u64 %0, t; }"
        : "=r"(a) : "l"(p));
    return a;
}

__device__ __forceinline__ void cp16(uint32_t dst, const void* src) {
    asm volatile("cp.async.cg.shared.global [%0], [%1], 16;" :: "r"(dst), "l"(src));
}
__device__ __forceinline__ void cp_commit() {
    asm volatile("cp.async.commit_group;" ::: "memory");
}

// ---------------------------------------------------------------------------
// split kernels: f32 -> bf16 hi/lo
// ---------------------------------------------------------------------------
__global__ void split_kernel(const float* __restrict__ src,
                             __nv_bfloat16* __restrict__ hi,
                             __nv_bfloat16* __restrict__ lo,
                             int n4, float scale)
{
    int i = blockIdx.x * blockDim.x + threadIdx.x;
    if (i >= n4) return;
    float4 v = ((const float4*)src)[i];
    uint32_t h0, l0, h1, l1;
    split2(v.x * scale, v.y * scale, h0, l0);
    split2(v.z * scale, v.w * scale, h1, l1);
    ((uint2*)hi)[i] = make_uint2(h0, h1);
    ((uint2*)lo)[i] = make_uint2(l0, l1);
}

// Wq (y==0) folds 1/8 * log2(e): scores come out pre-scaled for exp2.
__global__ void split4_kernel(const float* __restrict__ w0,
                              const float* __restrict__ w1,
                              const float* __restrict__ w2,
                              const float* __restrict__ w3,
                              __nv_bfloat16* __restrict__ hi,
                              __nv_bfloat16* __restrict__ lo, int n4)
{
    int i = blockIdx.x * blockDim.x + threadIdx.x;
    if (i >= n4) return;
    int y = blockIdx.y;
    const float* src = (y == 0) ? w0 : (y == 1) ? w1 : (y == 2) ? w2 : w3;
    float scale = (y == 0) ? (0.125f * L2E) : 1.0f;
    float4 v = ((const float4*)src)[i];
    uint32_t h0, l0, h1, l1;
    split2(v.x * scale, v.y * scale, h0, l0);
    split2(v.z * scale, v.w * scale, h1, l1);
    size_t o = (size_t)y * (Dq * (size_t)Dq / 4) + i;
    ((uint2*)hi)[o] = make_uint2(h0, h1);
    ((uint2*)lo)[o] = make_uint2(l0, l1);
}

// ---------------------------------------------------------------------------
// bf16x3 GEMM core (R14 measured shape, issue-floor ~93.5 us):
// 128x128 CTA tile, BK=32, double-buffered cp.async, warp tile 64x32.
// smem rows: 32 bf16 = 64B data, stride 80B. 81920 B smem -> 2 CTAs/SM.
// ---------------------------------------------------------------------------
#define GST 80
#define ATB (128*GST)
#define STAGE_B (4*ATB)
#define GEMM_SMEM (2*STAGE_B)

__device__ __forceinline__ void gemm_mainloop(
    uint32_t sb, int tid,
    const __nv_bfloat16* __restrict__ Ah, const __nv_bfloat16* __restrict__ Al,
    const __nv_bfloat16* __restrict__ Bh, const __nv_bfloat16* __restrict__ Bl,
    int m0, int n0, float acc[4][4][4])
{
    const int lane = tid & 31;
    const int q4 = lane >> 3, m8 = lane & 7;
    const int wid = tid >> 5;
    const int wm = wid & 1, wn = wid >> 1;

    const int grp = tid >> 6, tg = tid & 63;
    const __nv_bfloat16* msrc =
        (grp == 0) ? Ah + (size_t)m0 * Dq :
        (grp == 1) ? Al + (size_t)m0 * Dq :
        (grp == 2) ? Bh + (size_t)n0 * Dq : Bl + (size_t)n0 * Dq;
    const uint32_t aoff = grp * ATB;

    const uint32_t aRel = (uint32_t)((wm*64 + ((q4&1)<<3) + m8) * GST + ((q4>>1)<<4));
    const uint32_t bRel = (uint32_t)(2*ATB + (wn*32 + ((q4>>1)<<3) + m8) * GST + ((q4&1)<<4));

    {
#pragma unroll
        for (int i = 0; i < 8; i++) {
            int chunk = tg + 64 * i;
            int r = chunk >> 2, c = chunk & 3;
            cp16(sb + aoff + r * GST + c * 16, msrc + (size_t)r * Dq + c * 8);
        }
        cp_commit();
    }

    for (int it = 0; it < 32; it++) {
        const int buf = it & 1;
        const uint32_t stage = sb + buf * STAGE_B;
        if (it < 31) {
            const uint32_t nstage = sb + (buf ^ 1) * STAGE_B;
            const int k0 = (it + 1) * 32;
#pragma unroll
            for (int i = 0; i < 8; i++) {
                int chunk = tg + 64 * i;
                int r = chunk >> 2, c = chunk & 3;
                cp16(nstage + aoff + r * GST + c * 16,
                     msrc + (size_t)r * Dq + k0 + c * 8);
            }
            cp_commit();
            asm volatile("cp.async.wait_group 1;" ::: "memory");
        } else {
            asm volatile("cp.async.wait_group 0;" ::: "memory");
        }
        __syncthreads();

#pragma unroll
        for (int ks = 0; ks < 2; ks++) {
            uint32_t ah[4][4], al[4][4];
#pragma unroll
            for (int i = 0; i < 4; i++) {
                ldm_x4(ah[i], stage + aRel + i * (16*GST) + ks * 32);
                ldm_x4(al[i], stage + ATB + aRel + i * (16*GST) + ks * 32);
            }
#pragma unroll
            for (int jb = 0; jb < 2; jb++) {
                uint32_t bH[4], bL[4];
                ldm_x4(bH, stage + bRel + jb * (16*GST) + ks * 32);
                ldm_x4(bL, stage + ATB + bRel + jb * (16*GST) + ks * 32);
#pragma unroll
                for (int i = 0; i < 4; i++) {
                    mma16816(acc[i][2*jb],   ah[i], bH[0], bH[1]);
                    mma16816(acc[i][2*jb],   ah[i], bL[0], bL[1]);
                    mma16816(acc[i][2*jb],   al[i], bH[0], bH[1]);
                    mma16816(acc[i][2*jb+1], ah[i], bH[2], bH[3]);
                    mma16816(acc[i][2*jb+1], ah[i], bL[2], bL[3]);
                    mma16816(acc[i][2*jb+1], al[i], bH[2], bH[3]);
                }
            }
        }
        __syncthreads();
    }
}

__global__ void __launch_bounds__(256, 2) gemm_qkv(
    const __nv_bfloat16* __restrict__ Xh, const __nv_bfloat16* __restrict__ Xl,
    const __nv_bfloat16* __restrict__ WhB, const __nv_bfloat16* __restrict__ WlB,
    const float* __restrict__ bq, const float* __restrict__ bk,
    const float* __restrict__ bv,
    __nv_bfloat16* __restrict__ Qh, __nv_bfloat16* __restrict__ Ql,
    __nv_bfloat16* __restrict__ Kh, __nv_bfloat16* __restrict__ Kl,
    __nv_bfloat16* __restrict__ Vh, __nv_bfloat16* __restrict__ Vl)
{
    extern __shared__ char smem[];
    const uint32_t sb = smem_u32(smem);
    const int tid = threadIdx.x;
    const int z = blockIdx.z;
    const int m0 = blockIdx.y * 128, n0 = blockIdx.x * 128;
    const size_t WN = (size_t)Dq * Dq;

    const __nv_bfloat16* Bh = WhB + (size_t)z * WN;
    const __nv_bfloat16* Bl = WlB + (size_t)z * WN;
    const float* bias = (z == 0) ? bq : (z == 1) ? bk : bv;
    const float bscale = (z == 0) ? (0.125f * L2E) : 1.0f;
    __nv_bfloat16* outH = (z == 0) ? Qh : (z == 1) ? Kh : Vh;
    __nv_bfloat16* outL = (z == 0) ? Ql : (z == 1) ? Kl : Vl;

    float acc[4][4][4];
#pragma unroll
    for (int i = 0; i < 4; i++)
#pragma unroll
        for (int j = 0; j < 4; j++)
#pragma unroll
            for (int r = 0; r < 4; r++) acc[i][j][r] = 0.f;

    gemm_mainloop(sb, tid, Xh, Xl, Bh, Bl, m0, n0, acc);

    const int lane = tid & 31, wid = tid >> 5;
    const int g = lane >> 2, tig = lane & 3;
    const int wm = wid & 1, wn = wid >> 1;
#pragma unroll
    for (int j = 0; j < 4; j++) {
        int cc = n0 + wn*32 + 8*j + 2*tig;
        float b0 = bias[cc] * bscale, b1 = bias[cc + 1] * bscale;
#pragma unroll
        for (int i = 0; i < 4; i++) {
            int rr = m0 + wm*64 + 16*i + g;
            uint32_t h0, l0, h1, l1;
            split2(acc[i][j][0] + b0, acc[i][j][1] + b1, h0, l0);
            split2(acc[i][j][2] + b0, acc[i][j][3] + b1, h1, l1);
            size_t i0 = ((size_t)rr * Dq + cc) >> 1;
            size_t i1 = ((size_t)(rr + 8) * Dq + cc) >> 1;
            ((uint32_t*)outH)[i0] = h0; ((uint32_t*)outL)[i0] = l0;
            ((uint32_t*)outH)[i1] = h1; ((uint32_t*)outL)[i1] = l1;
        }
    }
}

__global__ void __launch_bounds__(256, 2) gemm_out(
    const __nv_bfloat16* __restrict__ Ah, const __nv_bfloat16* __restrict__ Al,
    const __nv_bfloat16* __restrict__ Bh, const __nv_bfloat16* __restrict__ Bl,
    const float* __restrict__ bias, float* __restrict__ outF)
{
    extern __shared__ char smem[];
    const uint32_t sb = smem_u32(smem);
    const int tid = threadIdx.x;
    const int m0 = blockIdx.y * 128, n0 = blockIdx.x * 128;

    float acc[4][4][4];
#pragma unroll
    for (int i = 0; i < 4; i++)
#pragma unroll
        for (int j = 0; j < 4; j++)
#pragma unroll
            for (int r = 0; r < 4; r++) acc[i][j][r] = 0.f;

    gemm_mainloop(sb, tid, Ah, Al, Bh, Bl, m0, n0, acc);

    const int lane = tid & 31, wid = tid >> 5;
    const int g = lane >> 2, tig = lane & 3;
    const int wm = wid & 1, wn = wid >> 1;
#pragma unroll
    for (int j = 0; j < 4; j++) {
        int cc = n0 + wn*32 + 8*j + 2*tig;
        float b0 = bias[cc], b1 = bias[cc + 1];
#pragma unroll
        for (int i = 0; i < 4; i++) {
            int rr = m0 + wm*64 + 16*i + g;
            *(float2*)(outF + (size_t)rr * Dq + cc) =
                make_float2(acc[i][j][0] + b0, acc[i][j][1] + b1);
            *(float2*)(outF + (size_t)(rr + 8) * Dq + cc) =
                make_float2(acc[i][j][2] + b0, acc[i][j][3] + b1);
        }
    }
}

// ---------------------------------------------------------------------------
// Flash attention: bf16x3 mma.sync + ldmatrix, K+V double-buffered (one
// sync + one wait per tile). exp2-based no-max softmax (log2e folded into
// Wq and the mask; scores bounded -> exact). DEFERRED l-reduction: raw
// per-thread partials, single 4-shuffle reduce after the loop. Softmax
// interleaved with PV in halves to overlap MUFU with tensor pipe.
// smem: Q 36864 + K 2x18432 + V 2x18432 = 110592 B -> 2 CTAs/SM.
// ---------------------------------------------------------------------------
#define ATT_QH 0
#define ATT_QL 18432
#define ATT_K0 36864
#define ATT_V0 73728
#define ATT_SMEM 110592

__global__ void __launch_bounds__(256, 2) attn_kernel(
    const __nv_bfloat16* __restrict__ Qh, const __nv_bfloat16* __restrict__ Ql,
    const __nv_bfloat16* __restrict__ Kh, const __nv_bfloat16* __restrict__ Kl,
    const __nv_bfloat16* __restrict__ Vh, const __nv_bfloat16* __restrict__ Vl,
    const float* __restrict__ mask,
    __nv_bfloat16* __restrict__ Ch, __nv_bfloat16* __restrict__ Cl)
{
    extern __shared__ char smem[];
    const uint32_t sbB = smem_u32(smem);

    const int tid = threadIdx.x;
    const int lane = tid & 31;
    const int wid = tid >> 5;
    const int g = lane >> 2, tig = lane & 3;
    const int bh = blockIdx.y;
    const int b = bh >> 4, h = bh & 15;
    const int q0 = blockIdx.x * 128;

    const size_t baseQ  = ((size_t)(b * Sq + q0)) * Dq + h * HDq;
    const size_t baseKV = ((size_t)(b * Sq)) * Dq + h * HDq;

    const int q4 = lane >> 3, m8 = lane & 7;
    const uint32_t aHb = sbB + ATT_QH + (16*wid + ((q4&1)<<3) + m8)*144 + ((q4>>1)<<4);
    const uint32_t aLb = aHb + (ATT_QL - ATT_QH);
    const uint32_t kRel = (((q4>>1)<<3) + m8)*144 + ((q4&1)<<4);
    const uint32_t vRel = (((q4&1)<<3) + m8)*144 + ((q4>>1)<<4);

    const int hg = tid >> 7, ht = tid & 127;
    const __nv_bfloat16* ksrc = hg ? Kl : Kh;
    const __nv_bfloat16* vsrc = hg ? Vl : Vh;
    const uint32_t hoff = hg * 9216;

    // ---- load Q tile (hi/lo), natural rows ----
    {
        const __nv_bfloat16* src = hg ? Ql : Qh;
        const uint32_t off = hg ? ATT_QL : ATT_QH;
#pragma unroll
        for (int i = 0; i < 8; i++) {
            int chunk = ht + 128 * i;
            int r = chunk >> 3, c = chunk & 7;
            uint4 v = ((const uint4*)(src + baseQ + (size_t)r * Dq))[c];
            *(uint4*)(smem + off + r * 144 + c * 16) = v;
        }
    }

    // preload K0 + V0 into slot 0
#pragma unroll
    for (int i = 0; i < 4; i++) {
        int chunk = ht + 128 * i;
        int r = chunk >> 3, c = chunk & 7;
        cp16(sbB + ATT_K0 + hoff + r * 144 + c * 16,
             ksrc + baseKV + (size_t)r * Dq + c * 8);
        cp16(sbB + ATT_V0 + hoff + r * 144 + c * 16,
             vsrc + baseKV + (size_t)r * Dq + c * 8);
    }
    cp_commit();

    float l0 = 0.f, l1 = 0.f;   // raw per-thread partials (reduced at end)
    float o[8][4];
#pragma unroll
    for (int jj = 0; jj < 8; jj++)
#pragma unroll
        for (int r = 0; r < 4; r++) o[jj][r] = 0.f;

    for (int t = 0; t < 32; t++) {
        const int k0 = t * 64;
        const uint32_t slot = (t & 1) * 18432;

        asm volatile("cp.async.wait_group 0;" ::: "memory");
        __syncthreads();

        // mask (pre-scaled by log2e) into registers
        float2 mreg[8];
        {
            const float2* mp = (const float2*)(mask + b * Sq + k0);
#pragma unroll
            for (int j = 0; j < 8; j++) {
                mreg[j] = mp[4*j + tig];
                mreg[j].x *= L2E; mreg[j].y *= L2E;
            }
        }

        // ---- S = Q K^T (already in log2 domain via Wq scale) ----
        const uint32_t kHb = sbB + ATT_K0 + slot + kRel;
        const uint32_t kLb = kHb + 9216;
        float s[8][4];
#pragma unroll
        for (int j = 0; j < 8; j++)
#pragma unroll
            for (int r = 0; r < 4; r++) s[j][r] = 0.f;

#pragma unroll
        for (int kb = 0; kb < 4; kb++) {
            uint32_t aH[4], aL[4];
            ldm_x4(aH, aHb + kb * 32);
            ldm_x4(aL, aLb + kb * 32);
#pragma unroll
            for (int jp = 0; jp < 4; jp++) {
                uint32_t bH[4], bL[4];
                ldm_x4(bH, kHb + jp * 2304 + kb * 32);
                ldm_x4(bL, kLb + jp * 2304 + kb * 32);
                mma16816(s[2*jp],   aH, bH[0], bH[1]);
                mma16816(s[2*jp],   aH, bL[0], bL[1]);
                mma16816(s[2*jp],   aL, bH[0], bH[1]);
                mma16816(s[2*jp+1], aH, bH[2], bH[3]);
                mma16816(s[2*jp+1], aH, bL[2], bL[3]);
                mma16816(s[2*jp+1], aL, bH[2], bH[3]);
            }
        }

        // issue K(t+1)+V(t+1) into the other slot
        if (t < 31) {
            const uint32_t nslot = ((t + 1) & 1) * 18432;
#pragma unroll
            for (int i = 0; i < 4; i++) {
                int chunk = ht + 128 * i;
                int r = chunk >> 3, c = chunk & 7;
                cp16(sbB + ATT_K0 + nslot + hoff + r * 144 + c * 16,
                     ksrc + baseKV + (size_t)(k0 + 64 + r) * Dq + c * 8);
                cp16(sbB + ATT_V0 + nslot + hoff + r * 144 + c * 16,
                     vsrc + baseKV + (size_t)(k0 + 64 + r) * Dq + c * 8);
            }
            cp_commit();
        }

        // ---- softmax (exp2, no shuffles) interleaved with PV in halves ----
        const uint32_t vHb = sbB + ATT_V0 + slot + vRel;
        const uint32_t vLb = vHb + 9216;
#pragma unroll
        for (int half = 0; half < 2; half++) {
            // exp2 + local sums for s[4h .. 4h+3]
#pragma unroll
            for (int jj = 0; jj < 4; jj++) {
                int j = 4*half + jj;
                s[j][0] = ex2(s[j][0] + mreg[j].x); l0 += s[j][0];
                s[j][1] = ex2(s[j][1] + mreg[j].y); l0 += s[j][1];
                s[j][2] = ex2(s[j][2] + mreg[j].x); l1 += s[j][2];
                s[j][3] = ex2(s[j][3] + mreg[j].y); l1 += s[j][3];
            }
            // pack P fragments for kb = 2h, 2h+1
            uint32_t ph[2][4], pl[2][4];
#pragma unroll
            for (int kk = 0; kk < 2; kk++) {
                int kb = 2*half + kk;
                split2(s[2*kb][0],   s[2*kb][1],   ph[kk][0], pl[kk][0]);
                split2(s[2*kb][2],   s[2*kb][3],   ph[kk][1], pl[kk][1]);
                split2(s[2*kb+1][0], s[2*kb+1][1], ph[kk][2], pl[kk][2]);
                split2(s[2*kb+1][2], s[2*kb+1][3], ph[kk][3], pl[kk][3]);
            }
            // PV for kb = 2h, 2h+1
#pragma unroll
            for (int kk = 0; kk < 2; kk++) {
                int kb = 2*half + kk;
#pragma unroll
                for (int jp = 0; jp < 4; jp++) {
                    uint32_t vH[4], vL[4];
                    ldm_x4_t(vH, vHb + kb * 2304 + jp * 32);
                    ldm_x4_t(vL, vLb + kb * 2304 + jp * 32);
                    mma16816(o[2*jp],   ph[kk], vH[0], vH[1]);
                    mma16816(o[2*jp],   ph[kk], vL[0], vL[1]);
                    mma16816(o[2*jp],   pl[kk], vH[0], vH[1]);
                    mma16816(o[2*jp+1], ph[kk], vH[2], vH[3]);
                    mma16816(o[2*jp+1], ph[kk], vL[2], vL[3]);
                    mma16816(o[2*jp+1], pl[kk], vH[2], vH[3]);
                }
            }
        }
    }

    // ---- single deferred l-reduction ----
    l0 += __shfl_xor_sync(0xffffffffu, l0, 1);
    l0 += __shfl_xor_sync(0xffffffffu, l0, 2);
    l1 += __shfl_xor_sync(0xffffffffu, l1, 1);
    l1 += __shfl_xor_sync(0xffffffffu, l1, 2);

    // ---- epilogue: ctx as bf16 hi/lo ----
    float inv0 = 1.0f / l0, inv1 = 1.0f / l1;
    size_t row0 = (size_t)(b * Sq + q0 + 16*wid + g);
#pragma unroll
    for (int jj = 0; jj < 8; jj++) {
        int cc = 8*jj + 2*tig;
        uint32_t h0, l0b, h1, l1b;
        split2(o[jj][0] * inv0, o[jj][1] * inv0, h0, l0b);
        split2(o[jj][2] * inv1, o[jj][3] * inv1, h1, l1b);
        size_t i0 = (row0 * Dq + h * HDq + cc) >> 1;
        size_t i1 = ((row0 + 8) * Dq + h * HDq + cc) >> 1;
        ((uint32_t*)Ch)[i0] = h0; ((uint32_t*)Cl)[i0] = l0b;
        ((uint32_t*)Ch)[i1] = h1; ((uint32_t*)Cl)[i1] = l1b;
    }
}

// ---------------------------------------------------------------------------

extern "C" void kernel_launch(void* const* d_in, const int* in_sizes, int n_in,
                              void* d_out, int out_size)
{
    const float* hs   = (const float*)d_in[0];
    const float* mask = (const float*)d_in[1];
    const float* Wq   = (const float*)d_in[2];
    const float* bq   = (const float*)d_in[3];
    const float* Wk   = (const float*)d_in[4];
    const float* bk   = (const float*)d_in[5];
    const float* Wv   = (const float*)d_in[6];
    const float* bv   = (const float*)d_in[7];
    const float* Wo   = (const float*)d_in[8];
    const float* bo   = (const float*)d_in[9];
    float* out = (float*)d_out;

    __nv_bfloat16 *xh, *xl, *wh, *wl, *qh, *ql, *kh, *kl, *vh, *vl, *ch, *cl;
    cudaGetSymbolAddress((void**)&xh, gXh); cudaGetSymbolAddress((void**)&xl, gXl);
    cudaGetSymbolAddress((void**)&wh, gWh); cudaGetSymbolAddress((void**)&wl, gWl);
    cudaGetSymbolAddress((void**)&qh, gQh); cudaGetSymbolAddress((void**)&ql, gQl);
    cudaGetSymbolAddress((void**)&kh, gKh); cudaGetSymbolAddress((void**)&kl, gKl);
    cudaGetSymbolAddress((void**)&vh, gVh); cudaGetSymbolAddress((void**)&vl, gVl);
    cudaGetSymbolAddress((void**)&ch, gCh); cudaGetSymbolAddress((void**)&cl, gCl);

    const int WN = Dq * Dq;

    split_kernel<<<(Mq*Dq/4 + 255)/256, 256>>>(hs, xh, xl, Mq*Dq/4, 1.0f);
    dim3 sgrid((WN/4 + 255)/256, 4);
    split4_kernel<<<sgrid, 256>>>(Wq, Wk, Wv, Wo, wh, wl, WN/4);

    cudaFuncSetAttribute(gemm_qkv, cudaFuncAttributeMaxDynamicSharedMemorySize, GEMM_SMEM);
    cudaFuncSetAttribute(gemm_out, cudaFuncAttributeMaxDynamicSharedMemorySize, GEMM_SMEM);

    dim3 qgrid(Dq / 128, Mq / 128, 3);
    gemm_qkv<<<qgrid, 256, GEMM_SMEM>>>(xh, xl, wh, wl, bq, bk, bv,
                                        qh, ql, kh, kl, vh, vl);

    cudaFuncSetAttribute(attn_kernel, cudaFuncAttributeMaxDynamicSharedMemorySize, ATT_SMEM);
    dim3 agrid(Sq / 128, Bq * Hq);
    attn_kernel<<<agrid, 256, ATT_SMEM>>>(qh, ql, kh, kl, vh, vl, mask, ch, cl);

    dim3 ggrid(Dq / 128, Mq / 128);
    gemm_out<<<ggrid, 256, GEMM_SMEM>>>(ch, cl, wh + 3*(size_t)WN, wl + 3*(size_t)WN,
                                        bo, out);
}

// round 17
// speedup vs baseline: 1.3284x; 1.0835x over previous
#include <cuda_runtime.h>
#include <cuda_bf16.h>
#include <cuda_fp16.h>
#include <cstdint>

#define Bq 2
#define Sq 2048
#define Dq 1024
#define Hq 16
#define HDq 64
#define Mq (Bq*Sq)
#define L2E 1.4426950408889634f

// ---------------- global scratch (allocation-free) ----------------
__device__ __align__(16) __nv_bfloat16 gXh[Mq*Dq], gXl[Mq*Dq];
__device__ __align__(16) __nv_bfloat16 gWh[4][Dq*Dq], gWl[4][Dq*Dq];
__device__ __align__(16) __nv_bfloat16 gQh[Mq*Dq], gQl[Mq*Dq];
__device__ __align__(16) __nv_bfloat16 gKh[Mq*Dq], gKl[Mq*Dq];
__device__ __align__(16) __nv_bfloat16 gVh[Mq*Dq], gVl[Mq*Dq];  // fp16 bits
__device__ __align__(16) __nv_bfloat16 gCh[Mq*Dq], gCl[Mq*Dq];

// ---------------- small helpers ----------------
__device__ __forceinline__ void split2(float x, float y,
                                       uint32_t& hi, uint32_t& lo) {
    __nv_bfloat16 hx = __float2bfloat16_rn(x);
    __nv_bfloat16 hy = __float2bfloat16_rn(y);
    __nv_bfloat162 h2 = __halves2bfloat162(hx, hy);
    __nv_bfloat162 l2 = __halves2bfloat162(
        __float2bfloat16_rn(x - __bfloat162float(hx)),
        __float2bfloat16_rn(y - __bfloat162float(hy)));
    hi = *reinterpret_cast<uint32_t*>(&h2);
    lo = *reinterpret_cast<uint32_t*>(&l2);
}

// fp16 hi/lo split (22-bit effective)
__device__ __forceinline__ void split2h(float x, float y,
                                        uint32_t& hi, uint32_t& lo) {
    __half hx = __float2half_rn(x);
    __half hy = __float2half_rn(y);
    __half2 h2 = __halves2half2(hx, hy);
    __half2 l2 = __halves2half2(
        __float2half_rn(x - __half2float(hx)),
        __float2half_rn(y - __half2float(hy)));
    hi = *reinterpret_cast<uint32_t*>(&h2);
    lo = *reinterpret_cast<uint32_t*>(&l2);
}

// pack two floats to f16x2 (x in low half)
__device__ __forceinline__ uint32_t pack_h2(float x, float y) {
    uint32_t d;
    asm("cvt.rn.f16x2.f32 %0, %1, %2;" : "=r"(d) : "f"(y), "f"(x));
    return d;
}

__device__ __forceinline__ float ex2(float x) {
    float y;
    asm("ex2.approx.f32 %0, %1;" : "=f"(y) : "f"(x));
    return y;
}

__device__ __forceinline__ void mma16816(float* c, const uint32_t* a,
                                         uint32_t b0, uint32_t b1) {
    asm volatile("mma.sync.aligned.m16n8k16.row.col.f32.bf16.bf16.f32 "
                 "{%0,%1,%2,%3}, {%4,%5,%6,%7}, {%8,%9}, {%0,%1,%2,%3};"
                 : "+f"(c[0]), "+f"(c[1]), "+f"(c[2]), "+f"(c[3])
                 : "r"(a[0]), "r"(a[1]), "r"(a[2]), "r"(a[3]),
                   "r"(b0), "r"(b1));
}

// fp16 variant
__device__ __forceinline__ void mma16816h(float* c, const uint32_t* a,
                                          uint32_t b0, uint32_t b1) {
    asm volatile("mma.sync.aligned.m16n8k16.row.col.f32.f16.f16.f32 "
                 "{%0,%1,%2,%3}, {%4,%5,%6,%7}, {%8,%9}, {%0,%1,%2,%3};"
                 : "+f"(c[0]), "+f"(c[1]), "+f"(c[2]), "+f"(c[3])
                 : "r"(a[0]), "r"(a[1]), "r"(a[2]), "r"(a[3]),
                   "r"(b0), "r"(b1));
}

__device__ __forceinline__ void ldm_x4(uint32_t* r, uint32_t a) {
    asm volatile("ldmatrix.sync.aligned.m8n8.x4.shared.b16 {%0,%1,%2,%3}, [%4];"
                 : "=r"(r[0]), "=r"(r[1]), "=r"(r[2]), "=r"(r[3]) : "r"(a));
}
__device__ __forceinline__ void ldm_x4_t(uint32_t* r, uint32_t a) {
    asm volatile("ldmatrix.sync.aligned.m8n8.x4.trans.shared.b16 {%0,%1,%2,%3}, [%4];"
                 : "=r"(r[0]), "=r"(r[1]), "=r"(r[2]), "=r"(r[3]) : "r"(a));
}

__device__ __forceinline__ uint32_t smem_u32(const void* p) {
    uint32_t a;
    asm("{ .reg .u64 t; cvta.to.shared.u64 t, %1; cvt.u32.u64 %0, t; }"
        : "=r"(a) : "l"(p));
    return a;
}

__device__ __forceinline__ void cp16(uint32_t dst, const void* src) {
    asm volatile("cp.async.cg.shared.global [%0], [%1], 16;" :: "r"(dst), "l"(src));
}
__device__ __forceinline__ void cp_commit() {
    asm volatile("cp.async.commit_group;" ::: "memory");
}

// ---------------------------------------------------------------------------
// split kernels: f32 -> bf16 hi/lo
// ---------------------------------------------------------------------------
__global__ void split_kernel(const float* __restrict__ src,
                             __nv_bfloat16* __restrict__ hi,
                             __nv_bfloat16* __restrict__ lo,
                             int n4, float scale)
{
    int i = blockIdx.x * blockDim.x + threadIdx.x;
    if (i >= n4) return;
    float4 v = ((const float4*)src)[i];
    uint32_t h0, l0, h1, l1;
    split2(v.x * scale, v.y * scale, h0, l0);
    split2(v.z * scale, v.w * scale, h1, l1);
    ((uint2*)hi)[i] = make_uint2(h0, h1);
    ((uint2*)lo)[i] = make_uint2(l0, l1);
}

// Wq (y==0) folds 1/8 * log2(e): scores come out pre-scaled for exp2.
__global__ void split4_kernel(const float* __restrict__ w0,
                              const float* __restrict__ w1,
                              const float* __restrict__ w2,
                              const float* __restrict__ w3,
                              __nv_bfloat16* __restrict__ hi,
                              __nv_bfloat16* __restrict__ lo, int n4)
{
    int i = blockIdx.x * blockDim.x + threadIdx.x;
    if (i >= n4) return;
    int y = blockIdx.y;
    const float* src = (y == 0) ? w0 : (y == 1) ? w1 : (y == 2) ? w2 : w3;
    float scale = (y == 0) ? (0.125f * L2E) : 1.0f;
    float4 v = ((const float4*)src)[i];
    uint32_t h0, l0, h1, l1;
    split2(v.x * scale, v.y * scale, h0, l0);
    split2(v.z * scale, v.w * scale, h1, l1);
    size_t o = (size_t)y * (Dq * (size_t)Dq / 4) + i;
    ((uint2*)hi)[o] = make_uint2(h0, h1);
    ((uint2*)lo)[o] = make_uint2(l0, l1);
}

// ---------------------------------------------------------------------------
// bf16x3 GEMM core (R14 measured shape):
// 128x128 CTA tile, BK=32, double-buffered cp.async, warp tile 64x32.
// smem rows: 32 bf16 = 64B data, stride 80B. 81920 B smem -> 2 CTAs/SM.
// ---------------------------------------------------------------------------
#define GST 80
#define ATB (128*GST)
#define STAGE_B (4*ATB)
#define GEMM_SMEM (2*STAGE_B)

__device__ __forceinline__ void gemm_mainloop(
    uint32_t sb, int tid,
    const __nv_bfloat16* __restrict__ Ah, const __nv_bfloat16* __restrict__ Al,
    const __nv_bfloat16* __restrict__ Bh, const __nv_bfloat16* __restrict__ Bl,
    int m0, int n0, float acc[4][4][4])
{
    const int lane = tid & 31;
    const int q4 = lane >> 3, m8 = lane & 7;
    const int wid = tid >> 5;
    const int wm = wid & 1, wn = wid >> 1;

    const int grp = tid >> 6, tg = tid & 63;
    const __nv_bfloat16* msrc =
        (grp == 0) ? Ah + (size_t)m0 * Dq :
        (grp == 1) ? Al + (size_t)m0 * Dq :
        (grp == 2) ? Bh + (size_t)n0 * Dq : Bl + (size_t)n0 * Dq;
    const uint32_t aoff = grp * ATB;

    const uint32_t aRel = (uint32_t)((wm*64 + ((q4&1)<<3) + m8) * GST + ((q4>>1)<<4));
    const uint32_t bRel = (uint32_t)(2*ATB + (wn*32 + ((q4>>1)<<3) + m8) * GST + ((q4&1)<<4));

    {
#pragma unroll
        for (int i = 0; i < 8; i++) {
            int chunk = tg + 64 * i;
            int r = chunk >> 2, c = chunk & 3;
            cp16(sb + aoff + r * GST + c * 16, msrc + (size_t)r * Dq + c * 8);
        }
        cp_commit();
    }

    for (int it = 0; it < 32; it++) {
        const int buf = it & 1;
        const uint32_t stage = sb + buf * STAGE_B;
        if (it < 31) {
            const uint32_t nstage = sb + (buf ^ 1) * STAGE_B;
            const int k0 = (it + 1) * 32;
#pragma unroll
            for (int i = 0; i < 8; i++) {
                int chunk = tg + 64 * i;
                int r = chunk >> 2, c = chunk & 3;
                cp16(nstage + aoff + r * GST + c * 16,
                     msrc + (size_t)r * Dq + k0 + c * 8);
            }
            cp_commit();
            asm volatile("cp.async.wait_group 1;" ::: "memory");
        } else {
            asm volatile("cp.async.wait_group 0;" ::: "memory");
        }
        __syncthreads();

#pragma unroll
        for (int ks = 0; ks < 2; ks++) {
            uint32_t ah[4][4], al[4][4];
#pragma unroll
            for (int i = 0; i < 4; i++) {
                ldm_x4(ah[i], stage + aRel + i * (16*GST) + ks * 32);
                ldm_x4(al[i], stage + ATB + aRel + i * (16*GST) + ks * 32);
            }
#pragma unroll
            for (int jb = 0; jb < 2; jb++) {
                uint32_t bH[4], bL[4];
                ldm_x4(bH, stage + bRel + jb * (16*GST) + ks * 32);
                ldm_x4(bL, stage + ATB + bRel + jb * (16*GST) + ks * 32);
#pragma unroll
                for (int i = 0; i < 4; i++) {
                    mma16816(acc[i][2*jb],   ah[i], bH[0], bH[1]);
                    mma16816(acc[i][2*jb],   ah[i], bL[0], bL[1]);
                    mma16816(acc[i][2*jb],   al[i], bH[0], bH[1]);
                    mma16816(acc[i][2*jb+1], ah[i], bH[2], bH[3]);
                    mma16816(acc[i][2*jb+1], ah[i], bL[2], bL[3]);
                    mma16816(acc[i][2*jb+1], al[i], bH[2], bH[3]);
                }
            }
        }
        __syncthreads();
    }
}

// Fused QKV. z==2 (V) emits fp16 hi/lo (for the fp16 PV path); Q/K bf16.
__global__ void __launch_bounds__(256, 2) gemm_qkv(
    const __nv_bfloat16* __restrict__ Xh, const __nv_bfloat16* __restrict__ Xl,
    const __nv_bfloat16* __restrict__ WhB, const __nv_bfloat16* __restrict__ WlB,
    const float* __restrict__ bq, const float* __restrict__ bk,
    const float* __restrict__ bv,
    __nv_bfloat16* __restrict__ Qh, __nv_bfloat16* __restrict__ Ql,
    __nv_bfloat16* __restrict__ Kh, __nv_bfloat16* __restrict__ Kl,
    __nv_bfloat16* __restrict__ Vh, __nv_bfloat16* __restrict__ Vl)
{
    extern __shared__ char smem[];
    const uint32_t sb = smem_u32(smem);
    const int tid = threadIdx.x;
    const int z = blockIdx.z;
    const int m0 = blockIdx.y * 128, n0 = blockIdx.x * 128;
    const size_t WN = (size_t)Dq * Dq;

    const __nv_bfloat16* Bh = WhB + (size_t)z * WN;
    const __nv_bfloat16* Bl = WlB + (size_t)z * WN;
    const float* bias = (z == 0) ? bq : (z == 1) ? bk : bv;
    const float bscale = (z == 0) ? (0.125f * L2E) : 1.0f;
    __nv_bfloat16* outH = (z == 0) ? Qh : (z == 1) ? Kh : Vh;
    __nv_bfloat16* outL = (z == 0) ? Ql : (z == 1) ? Kl : Vl;

    float acc[4][4][4];
#pragma unroll
    for (int i = 0; i < 4; i++)
#pragma unroll
        for (int j = 0; j < 4; j++)
#pragma unroll
            for (int r = 0; r < 4; r++) acc[i][j][r] = 0.f;

    gemm_mainloop(sb, tid, Xh, Xl, Bh, Bl, m0, n0, acc);

    const int lane = tid & 31, wid = tid >> 5;
    const int g = lane >> 2, tig = lane & 3;
    const int wm = wid & 1, wn = wid >> 1;
#pragma unroll
    for (int j = 0; j < 4; j++) {
        int cc = n0 + wn*32 + 8*j + 2*tig;
        float b0 = bias[cc] * bscale, b1 = bias[cc + 1] * bscale;
#pragma unroll
        for (int i = 0; i < 4; i++) {
            int rr = m0 + wm*64 + 16*i + g;
            uint32_t h0, l0, h1, l1;
            if (z == 2) {
                split2h(acc[i][j][0] + b0, acc[i][j][1] + b1, h0, l0);
                split2h(acc[i][j][2] + b0, acc[i][j][3] + b1, h1, l1);
            } else {
                split2(acc[i][j][0] + b0, acc[i][j][1] + b1, h0, l0);
                split2(acc[i][j][2] + b0, acc[i][j][3] + b1, h1, l1);
            }
            size_t i0 = ((size_t)rr * Dq + cc) >> 1;
            size_t i1 = ((size_t)(rr + 8) * Dq + cc) >> 1;
            ((uint32_t*)outH)[i0] = h0; ((uint32_t*)outL)[i0] = l0;
            ((uint32_t*)outH)[i1] = h1; ((uint32_t*)outL)[i1] = l1;
        }
    }
}

__global__ void __launch_bounds__(256, 2) gemm_out(
    const __nv_bfloat16* __restrict__ Ah, const __nv_bfloat16* __restrict__ Al,
    const __nv_bfloat16* __restrict__ Bh, const __nv_bfloat16* __restrict__ Bl,
    const float* __restrict__ bias, float* __restrict__ outF)
{
    extern __shared__ char smem[];
    const uint32_t sb = smem_u32(smem);
    const int tid = threadIdx.x;
    const int m0 = blockIdx.y * 128, n0 = blockIdx.x * 128;

    float acc[4][4][4];
#pragma unroll
    for (int i = 0; i < 4; i++)
#pragma unroll
        for (int j = 0; j < 4; j++)
#pragma unroll
            for (int r = 0; r < 4; r++) acc[i][j][r] = 0.f;

    gemm_mainloop(sb, tid, Ah, Al, Bh, Bl, m0, n0, acc);

    const int lane = tid & 31, wid = tid >> 5;
    const int g = lane >> 2, tig = lane & 3;
    const int wm = wid & 1, wn = wid >> 1;
#pragma unroll
    for (int j = 0; j < 4; j++) {
        int cc = n0 + wn*32 + 8*j + 2*tig;
        float b0 = bias[cc], b1 = bias[cc + 1];
#pragma unroll
        for (int i = 0; i < 4; i++) {
            int rr = m0 + wm*64 + 16*i + g;
            *(float2*)(outF + (size_t)rr * Dq + cc) =
                make_float2(acc[i][j][0] + b0, acc[i][j][1] + b1);
            *(float2*)(outF + (size_t)(rr + 8) * Dq + cc) =
                make_float2(acc[i][j][2] + b0, acc[i][j][3] + b1);
        }
    }
}

// ---------------------------------------------------------------------------
// Flash attention: QK in bf16x3 (score precision), PV in fp16 2-term
// (P single fp16, V fp16 hi/lo) -> per-tile mma 192 -> 160. K+V double-
// buffered (one sync + wait per tile). exp2 no-max softmax, deferred
// l-reduction. smem 110592 B -> 2 CTAs/SM.
// ---------------------------------------------------------------------------
#define ATT_QH 0
#define ATT_QL 18432
#define ATT_K0 36864
#define ATT_V0 73728
#define ATT_SMEM 110592

__global__ void __launch_bounds__(256, 2) attn_kernel(
    const __nv_bfloat16* __restrict__ Qh, const __nv_bfloat16* __restrict__ Ql,
    const __nv_bfloat16* __restrict__ Kh, const __nv_bfloat16* __restrict__ Kl,
    const __nv_bfloat16* __restrict__ Vh, const __nv_bfloat16* __restrict__ Vl,
    const float* __restrict__ mask,
    __nv_bfloat16* __restrict__ Ch, __nv_bfloat16* __restrict__ Cl)
{
    extern __shared__ char smem[];
    const uint32_t sbB = smem_u32(smem);

    const int tid = threadIdx.x;
    const int lane = tid & 31;
    const int wid = tid >> 5;
    const int g = lane >> 2, tig = lane & 3;
    const int bh = blockIdx.y;
    const int b = bh >> 4, h = bh & 15;
    const int q0 = blockIdx.x * 128;

    const size_t baseQ  = ((size_t)(b * Sq + q0)) * Dq + h * HDq;
    const size_t baseKV = ((size_t)(b * Sq)) * Dq + h * HDq;

    const int q4 = lane >> 3, m8 = lane & 7;
    const uint32_t aHb = sbB + ATT_QH + (16*wid + ((q4&1)<<3) + m8)*144 + ((q4>>1)<<4);
    const uint32_t aLb = aHb + (ATT_QL - ATT_QH);
    const uint32_t kRel = (((q4>>1)<<3) + m8)*144 + ((q4&1)<<4);
    const uint32_t vRel = (((q4&1)<<3) + m8)*144 + ((q4>>1)<<4);

    const int hg = tid >> 7, ht = tid & 127;
    const __nv_bfloat16* ksrc = hg ? Kl : Kh;
    const __nv_bfloat16* vsrc = hg ? Vl : Vh;
    const uint32_t hoff = hg * 9216;

    // ---- load Q tile (hi/lo), natural rows ----
    {
        const __nv_bfloat16* src = hg ? Ql : Qh;
        const uint32_t off = hg ? ATT_QL : ATT_QH;
#pragma unroll
        for (int i = 0; i < 8; i++) {
            int chunk = ht + 128 * i;
            int r = chunk >> 3, c = chunk & 7;
            uint4 v = ((const uint4*)(src + baseQ + (size_t)r * Dq))[c];
            *(uint4*)(smem + off + r * 144 + c * 16) = v;
        }
    }

    // preload K0 + V0 into slot 0
#pragma unroll
    for (int i = 0; i < 4; i++) {
        int chunk = ht + 128 * i;
        int r = chunk >> 3, c = chunk & 7;
        cp16(sbB + ATT_K0 + hoff + r * 144 + c * 16,
             ksrc + baseKV + (size_t)r * Dq + c * 8);
        cp16(sbB + ATT_V0 + hoff + r * 144 + c * 16,
             vsrc + baseKV + (size_t)r * Dq + c * 8);
    }
    cp_commit();

    float l0 = 0.f, l1 = 0.f;   // raw per-thread partials
    float o[8][4];
#pragma unroll
    for (int jj = 0; jj < 8; jj++)
#pragma unroll
        for (int r = 0; r < 4; r++) o[jj][r] = 0.f;

    for (int t = 0; t < 32; t++) {
        const int k0 = t * 64;
        const uint32_t slot = (t & 1) * 18432;

        asm volatile("cp.async.wait_group 0;" ::: "memory");
        __syncthreads();

        // mask (pre-scaled by log2e) into registers
        float2 mreg[8];
        {
            const float2* mp = (const float2*)(mask + b * Sq + k0);
#pragma unroll
            for (int j = 0; j < 8; j++) {
                mreg[j] = mp[4*j + tig];
                mreg[j].x *= L2E; mreg[j].y *= L2E;
            }
        }

        // ---- S = Q K^T (bf16x3, log2 domain) ----
        const uint32_t kHb = sbB + ATT_K0 + slot + kRel;
        const uint32_t kLb = kHb + 9216;
        float s[8][4];
#pragma unroll
        for (int j = 0; j < 8; j++)
#pragma unroll
            for (int r = 0; r < 4; r++) s[j][r] = 0.f;

#pragma unroll
        for (int kb = 0; kb < 4; kb++) {
            uint32_t aH[4], aL[4];
            ldm_x4(aH, aHb + kb * 32);
            ldm_x4(aL, aLb + kb * 32);
#pragma unroll
            for (int jp = 0; jp < 4; jp++) {
                uint32_t bH[4], bL[4];
                ldm_x4(bH, kHb + jp * 2304 + kb * 32);
                ldm_x4(bL, kLb + jp * 2304 + kb * 32);
                mma16816(s[2*jp],   aH, bH[0], bH[1]);
                mma16816(s[2*jp],   aH, bL[0], bL[1]);
                mma16816(s[2*jp],   aL, bH[0], bH[1]);
                mma16816(s[2*jp+1], aH, bH[2], bH[3]);
                mma16816(s[2*jp+1], aH, bL[2], bL[3]);
                mma16816(s[2*jp+1], aL, bH[2], bH[3]);
            }
        }

        // issue K(t+1)+V(t+1) into the other slot
        if (t < 31) {
            const uint32_t nslot = ((t + 1) & 1) * 18432;
#pragma unroll
            for (int i = 0; i < 4; i++) {
                int chunk = ht + 128 * i;
                int r = chunk >> 3, c = chunk & 7;
                cp16(sbB + ATT_K0 + nslot + hoff + r * 144 + c * 16,
                     ksrc + baseKV + (size_t)(k0 + 64 + r) * Dq + c * 8);
                cp16(sbB + ATT_V0 + nslot + hoff + r * 144 + c * 16,
                     vsrc + baseKV + (size_t)(k0 + 64 + r) * Dq + c * 8);
            }
            cp_commit();
        }

        // ---- softmax (exp2) + fp16 PV, interleaved in halves ----
        const uint32_t vHb = sbB + ATT_V0 + slot + vRel;
        const uint32_t vLb = vHb + 9216;
#pragma unroll
        for (int half = 0; half < 2; half++) {
#pragma unroll
            for (int jj = 0; jj < 4; jj++) {
                int j = 4*half + jj;
                s[j][0] = ex2(s[j][0] + mreg[j].x); l0 += s[j][0];
                s[j][1] = ex2(s[j][1] + mreg[j].y); l0 += s[j][1];
                s[j][2] = ex2(s[j][2] + mreg[j].x); l1 += s[j][2];
                s[j][3] = ex2(s[j][3] + mreg[j].y); l1 += s[j][3];
            }
            // P fragments: single fp16 (2.8e-4 rel, unbiased)
            uint32_t ph[2][4];
#pragma unroll
            for (int kk = 0; kk < 2; kk++) {
                int kb = 2*half + kk;
                ph[kk][0] = pack_h2(s[2*kb][0],   s[2*kb][1]);
                ph[kk][1] = pack_h2(s[2*kb][2],   s[2*kb][3]);
                ph[kk][2] = pack_h2(s[2*kb+1][0], s[2*kb+1][1]);
                ph[kk][3] = pack_h2(s[2*kb+1][2], s[2*kb+1][3]);
            }
            // PV: 2-term fp16 (Ph*Vh + Ph*Vl)
#pragma unroll
            for (int kk = 0; kk < 2; kk++) {
                int kb = 2*half + kk;
#pragma unroll
                for (int jp = 0; jp < 4; jp++) {
                    uint32_t vH[4], vL[4];
                    ldm_x4_t(vH, vHb + kb * 2304 + jp * 32);
                    ldm_x4_t(vL, vLb + kb * 2304 + jp * 32);
                    mma16816h(o[2*jp],   ph[kk], vH[0], vH[1]);
                    mma16816h(o[2*jp],   ph[kk], vL[0], vL[1]);
                    mma16816h(o[2*jp+1], ph[kk], vH[2], vH[3]);
                    mma16816h(o[2*jp+1], ph[kk], vL[2], vL[3]);
                }
            }
        }
    }

    // ---- single deferred l-reduction ----
    l0 += __shfl_xor_sync(0xffffffffu, l0, 1);
    l0 += __shfl_xor_sync(0xffffffffu, l0, 2);
    l1 += __shfl_xor_sync(0xffffffffu, l1, 1);
    l1 += __shfl_xor_sync(0xffffffffu, l1, 2);

    // ---- epilogue: ctx as bf16 hi/lo ----
    float inv0 = 1.0f / l0, inv1 = 1.0f / l1;
    size_t row0 = (size_t)(b * Sq + q0 + 16*wid + g);
#pragma unroll
    for (int jj = 0; jj < 8; jj++) {
        int cc = 8*jj + 2*tig;
        uint32_t h0, l0b, h1, l1b;
        split2(o[jj][0] * inv0, o[jj][1] * inv0, h0, l0b);
        split2(o[jj][2] * inv1, o[jj][3] * inv1, h1, l1b);
        size_t i0 = (row0 * Dq + h * HDq + cc) >> 1;
        size_t i1 = ((row0 + 8) * Dq + h * HDq + cc) >> 1;
        ((uint32_t*)Ch)[i0] = h0; ((uint32_t*)Cl)[i0] = l0b;
        ((uint32_t*)Ch)[i1] = h1; ((uint32_t*)Cl)[i1] = l1b;
    }
}

// ---------------------------------------------------------------------------

extern "C" void kernel_launch(void* const* d_in, const int* in_sizes, int n_in,
                              void* d_out, int out_size)
{
    const float* hs   = (const float*)d_in[0];
    const float* mask = (const float*)d_in[1];
    const float* Wq   = (const float*)d_in[2];
    const float* bq   = (const float*)d_in[3];
    const float* Wk   = (const float*)d_in[4];
    const float* bk   = (const float*)d_in[5];
    const float* Wv   = (const float*)d_in[6];
    const float* bv   = (const float*)d_in[7];
    const float* Wo   = (const float*)d_in[8];
    const float* bo   = (const float*)d_in[9];
    float* out = (float*)d_out;

    __nv_bfloat16 *xh, *xl, *wh, *wl, *qh, *ql, *kh, *kl, *vh, *vl, *ch, *cl;
    cudaGetSymbolAddress((void**)&xh, gXh); cudaGetSymbolAddress((void**)&xl, gXl);
    cudaGetSymbolAddress((void**)&wh, gWh); cudaGetSymbolAddress((void**)&wl, gWl);
    cudaGetSymbolAddress((void**)&qh, gQh); cudaGetSymbolAddress((void**)&ql, gQl);
    cudaGetSymbolAddress((void**)&kh, gKh); cudaGetSymbolAddress((void**)&kl, gKl);
    cudaGetSymbolAddress((void**)&vh, gVh); cudaGetSymbolAddress((void**)&vl, gVl);
    cudaGetSymbolAddress((void**)&ch, gCh); cudaGetSymbolAddress((void**)&cl, gCl);

    const int WN = Dq * Dq;

    split_kernel<<<(Mq*Dq/4 + 255)/256, 256>>>(hs, xh, xl, Mq*Dq/4, 1.0f);
    dim3 sgrid((WN/4 + 255)/256, 4);
    split4_kernel<<<sgrid, 256>>>(Wq, Wk, Wv, Wo, wh, wl, WN/4);

    cudaFuncSetAttribute(gemm_qkv, cudaFuncAttributeMaxDynamicSharedMemorySize, GEMM_SMEM);
    cudaFuncSetAttribute(gemm_out, cudaFuncAttributeMaxDynamicSharedMemorySize, GEMM_SMEM);

    dim3 qgrid(Dq / 128, Mq / 128, 3);
    gemm_qkv<<<qgrid, 256, GEMM_SMEM>>>(xh, xl, wh, wl, bq, bk, bv,
                                        qh, ql, kh, kl, vh, vl);

    cudaFuncSetAttribute(attn_kernel, cudaFuncAttributeMaxDynamicSharedMemorySize, ATT_SMEM);
    dim3 agrid(Sq / 128, Bq * Hq);
    attn_kernel<<<agrid, 256, ATT_SMEM>>>(qh, ql, kh, kl, vh, vl, mask, ch, cl);

    dim3 ggrid(Dq / 128, Mq / 128);
    gemm_out<<<ggrid, 256, GEMM_SMEM>>>(ch, cl, wh + 3*(size_t)WN, wl + 3*(size_t)WN,
                                        bo, out);
}